// round 1
// baseline (speedup 1.0000x reference)
#include <cuda_runtime.h>

#define BB 8
#define TT 2048
#define EE 1024
#define HH 64
#define RTOT (BB*TT)

// scratch for q,k,v projections (device globals: allocation-free)
__device__ float g_q[RTOT*HH];
__device__ float g_k[RTOT*HH];
__device__ float g_v[RTOT*HH];

// ---------------------------------------------------------------------------
// Kernel 1: fused QKV projection  out[m] = x @ W[m] + b[m]
// C[16384,64] per matrix; tile BM=128 rows x 64 cols, BK=32.
// 256 threads, each computes 8x4 micro-tile.
// ---------------------------------------------------------------------------
#define BM1 128
#define BK1 32

__global__ __launch_bounds__(256) void qkv_kernel(
    const float* __restrict__ x,
    const float* __restrict__ Wq, const float* __restrict__ bq,
    const float* __restrict__ Wk, const float* __restrict__ bk,
    const float* __restrict__ Wv, const float* __restrict__ bv)
{
    const int m = blockIdx.y;
    const float* W    = (m == 0) ? Wq : (m == 1 ? Wk : Wv);
    const float* bias = (m == 0) ? bq : (m == 1 ? bk : bv);
    float* out        = (m == 0) ? g_q : (m == 1 ? g_k : g_v);

    __shared__ float Xs[BK1][BM1];   // transposed: Xs[k][row]
    __shared__ float Ws[BK1][HH];    // Ws[k][h]

    const int tid = threadIdx.x;
    const int tx = tid & 15;         // 0..15 -> 4 cols each
    const int ty = tid >> 4;         // 0..15 -> 8 rows each
    const int row0 = blockIdx.x * BM1;

    float acc[8][4];
    #pragma unroll
    for (int r = 0; r < 8; r++)
        #pragma unroll
        for (int c = 0; c < 4; c++) acc[r][c] = 0.f;

    for (int k0 = 0; k0 < EE; k0 += BK1) {
        // load X tile (128 rows x 32 k), transpose into smem
        #pragma unroll
        for (int i = 0; i < 4; i++) {
            int idx = tid + i * 256;        // 0..1023
            int r   = idx >> 3;             // 0..127
            int kg  = idx & 7;              // float4 group (k)
            float4 v4 = *(const float4*)(x + (size_t)(row0 + r) * EE + k0 + kg * 4);
            Xs[kg*4+0][r] = v4.x;
            Xs[kg*4+1][r] = v4.y;
            Xs[kg*4+2][r] = v4.z;
            Xs[kg*4+3][r] = v4.w;
        }
        // load W tile (32 k x 64 h)
        #pragma unroll
        for (int i = 0; i < 2; i++) {
            int idx = tid + i * 256;        // 0..511
            int kk  = idx >> 4;             // 0..31
            int hg  = idx & 15;             // 0..15
            *(float4*)&Ws[kk][hg*4] =
                *(const float4*)(W + (size_t)(k0 + kk) * HH + hg * 4);
        }
        __syncthreads();

        #pragma unroll
        for (int kk = 0; kk < BK1; kk++) {
            float a[8], bw[4];
            *(float4*)&a[0] = *(float4*)&Xs[kk][ty*8];
            *(float4*)&a[4] = *(float4*)&Xs[kk][ty*8+4];
            *(float4*)&bw[0] = *(float4*)&Ws[kk][tx*4];
            #pragma unroll
            for (int r = 0; r < 8; r++)
                #pragma unroll
                for (int c = 0; c < 4; c++)
                    acc[r][c] += a[r] * bw[c];
        }
        __syncthreads();
    }

    float4 b4 = *(const float4*)(bias + tx*4);
    #pragma unroll
    for (int r = 0; r < 8; r++) {
        int orow = row0 + ty*8 + r;
        float4 o;
        o.x = acc[r][0] + b4.x;
        o.y = acc[r][1] + b4.y;
        o.z = acc[r][2] + b4.z;
        o.w = acc[r][3] + b4.w;
        *(float4*)(out + (size_t)orow * HH + tx*4) = o;
    }
}

// ---------------------------------------------------------------------------
// Kernel 2: causal flash attention (online softmax), fp32 SIMT.
// BM=64 query rows per block, BN=32 key cols per iteration, H=64.
// 256 threads; S micro-tile 4x2 per thread, O micro-tile 4x4.
// Static smem: 42 KB (< 48 KB, no attribute calls needed).
// ---------------------------------------------------------------------------
#define BMA 64
#define BNA 32
#define PPITCH 33   // (33r + j) mod 32 = (r + j) mod 32 -> conflict-free row scans

__global__ __launch_bounds__(256) void attn_kernel(float* __restrict__ out)
{
    __shared__ float Qs[HH * BMA];          // Qs[h][i]   (transposed)
    __shared__ float Ks[HH * BNA];          // Ks[h][j]   (transposed)
    __shared__ float Vs[BNA * HH];          // Vs[j][h]
    __shared__ float Ps[BMA * PPITCH];      // P / S tile
    __shared__ float rowm[BMA], rowl[BMA], rowf[BMA];

    const int qt  = blockIdx.x;             // 0..31
    const int b   = blockIdx.y;             // 0..7
    const int tid = threadIdx.x;
    const int tx  = tid & 15;
    const int ty  = tid >> 4;

    // load Q tile transposed: 64 rows x 64 h
    const float* qbase = g_q + (size_t)(b*TT + qt*BMA) * HH;
    #pragma unroll
    for (int i = 0; i < 4; i++) {
        int idx = tid + i * 256;            // 0..1023
        int row = idx >> 4;                 // 0..63
        int hg  = idx & 15;
        float4 v = *(const float4*)(qbase + (size_t)row * HH + hg*4);
        Qs[(hg*4+0)*BMA + row] = v.x;
        Qs[(hg*4+1)*BMA + row] = v.y;
        Qs[(hg*4+2)*BMA + row] = v.z;
        Qs[(hg*4+3)*BMA + row] = v.w;
    }
    if (tid < BMA) { rowm[tid] = -1e30f; rowl[tid] = 0.f; }

    float O[4][4];
    #pragma unroll
    for (int r = 0; r < 4; r++)
        #pragma unroll
        for (int c = 0; c < 4; c++) O[r][c] = 0.f;

    const int ktmax = 2*qt + 1;             // last K tile overlapping causal region
    for (int kt = 0; kt <= ktmax; kt++) {
        __syncthreads();                    // protect Ks/Vs/Ps from prev-iter readers

        // load K (transposed) + V tiles: 32 rows x 64 h each
        const float* kbase = g_k + (size_t)(b*TT + kt*BNA) * HH;
        const float* vbase = g_v + (size_t)(b*TT + kt*BNA) * HH;
        #pragma unroll
        for (int i = 0; i < 2; i++) {
            int idx = tid + i * 256;        // 0..511
            int row = idx >> 4;             // 0..31
            int hg  = idx & 15;
            float4 kv = *(const float4*)(kbase + (size_t)row * HH + hg*4);
            Ks[(hg*4+0)*BNA + row] = kv.x;
            Ks[(hg*4+1)*BNA + row] = kv.y;
            Ks[(hg*4+2)*BNA + row] = kv.z;
            Ks[(hg*4+3)*BNA + row] = kv.w;
            float4 vv = *(const float4*)(vbase + (size_t)row * HH + hg*4);
            *(float4*)&Vs[row*HH + hg*4] = vv;
        }
        __syncthreads();

        // S = Q @ K^T  (4 rows x 2 cols per thread)
        float s[4][2];
        #pragma unroll
        for (int r = 0; r < 4; r++) { s[r][0] = 0.f; s[r][1] = 0.f; }
        #pragma unroll 8
        for (int h = 0; h < HH; h++) {
            float4 qv = *(float4*)&Qs[h*BMA + ty*4];
            float2 kv = *(float2*)&Ks[h*BNA + tx*2];
            s[0][0] += qv.x * kv.x; s[0][1] += qv.x * kv.y;
            s[1][0] += qv.y * kv.x; s[1][1] += qv.y * kv.y;
            s[2][0] += qv.z * kv.x; s[2][1] += qv.z * kv.y;
            s[3][0] += qv.w * kv.x; s[3][1] += qv.w * kv.y;
        }
        // scale, causal mask, write S tile
        #pragma unroll
        for (int r = 0; r < 4; r++) {
            int qg = qt*BMA + ty*4 + r;
            #pragma unroll
            for (int c = 0; c < 2; c++) {
                int kg = kt*BNA + tx*2 + c;
                float val = s[r][c] * 0.125f;     // 1/sqrt(64)
                if (kg > qg) val = -1e30f;
                Ps[(ty*4+r)*PPITCH + tx*2 + c] = val;
            }
        }
        __syncthreads();

        // online softmax per row (64 rows by first 64 threads)
        if (tid < BMA) {
            int r = tid;
            float mold = rowm[r];
            float mt = mold;
            #pragma unroll 8
            for (int j = 0; j < BNA; j++)
                mt = fmaxf(mt, Ps[r*PPITCH + j]);
            float sum = 0.f;
            #pragma unroll 8
            for (int j = 0; j < BNA; j++) {
                float p = __expf(Ps[r*PPITCH + j] - mt);
                Ps[r*PPITCH + j] = p;
                sum += p;
            }
            float f = __expf(mold - mt);
            rowl[r] = rowl[r] * f + sum;
            rowf[r] = f;
            rowm[r] = mt;
        }
        __syncthreads();

        // O = O * f + P @ V   (4 rows x 4 h-cols per thread)
        float f[4];
        #pragma unroll
        for (int r = 0; r < 4; r++) f[r] = rowf[ty*4 + r];
        #pragma unroll
        for (int r = 0; r < 4; r++)
            #pragma unroll
            for (int c = 0; c < 4; c++) O[r][c] *= f[r];
        #pragma unroll 4
        for (int k = 0; k < BNA; k++) {
            float p0 = Ps[(ty*4+0)*PPITCH + k];
            float p1 = Ps[(ty*4+1)*PPITCH + k];
            float p2 = Ps[(ty*4+2)*PPITCH + k];
            float p3 = Ps[(ty*4+3)*PPITCH + k];
            float4 vv = *(float4*)&Vs[k*HH + tx*4];
            O[0][0] += p0*vv.x; O[0][1] += p0*vv.y; O[0][2] += p0*vv.z; O[0][3] += p0*vv.w;
            O[1][0] += p1*vv.x; O[1][1] += p1*vv.y; O[1][2] += p1*vv.z; O[1][3] += p1*vv.w;
            O[2][0] += p2*vv.x; O[2][1] += p2*vv.y; O[2][2] += p2*vv.z; O[2][3] += p2*vv.w;
            O[3][0] += p3*vv.x; O[3][1] += p3*vv.y; O[3][2] += p3*vv.z; O[3][3] += p3*vv.w;
        }
    }

    // finalize: divide by l, write out
    #pragma unroll
    for (int r = 0; r < 4; r++) {
        float inv = 1.0f / rowl[ty*4 + r];
        int orow = b*TT + qt*BMA + ty*4 + r;
        float4 o;
        o.x = O[r][0] * inv;
        o.y = O[r][1] * inv;
        o.z = O[r][2] * inv;
        o.w = O[r][3] * inv;
        *(float4*)(out + (size_t)orow * HH + tx*4) = o;
    }
}

// ---------------------------------------------------------------------------
extern "C" void kernel_launch(void* const* d_in, const int* in_sizes, int n_in,
                              void* d_out, int out_size)
{
    const float* x  = (const float*)d_in[0];
    const float* Wq = (const float*)d_in[1];
    const float* bq = (const float*)d_in[2];
    const float* Wk = (const float*)d_in[3];
    const float* bk = (const float*)d_in[4];
    const float* Wv = (const float*)d_in[5];
    const float* bv = (const float*)d_in[6];
    float* out = (float*)d_out;

    dim3 g1(RTOT / BM1, 3);
    qkv_kernel<<<g1, 256>>>(x, Wq, bq, Wk, bk, Wv, bv);

    dim3 g2(TT / BMA, BB);
    attn_kernel<<<g2, 256>>>(out);
}

// round 4
// speedup vs baseline: 1.3520x; 1.3520x over previous
#include <cuda_runtime.h>

#define BB 8
#define TT 2048
#define EE 1024
#define HH 64

// scratch for q,k,v projections (device globals: allocation-free)
__device__ float g_q[BB*TT*HH];
__device__ float g_k[BB*TT*HH];
__device__ float g_v[BB*TT*HH];

// ---------------------------------------------------------------------------
// Kernel 1: fused QKV projection. One block computes q,k,v for 64 rows.
// BM=64, BN=192 (all three heads), BK=16, 256 threads, micro-tile 4x(3x4).
// Register-staged prefetch overlaps LDG with FMA.
// ---------------------------------------------------------------------------
__global__ __launch_bounds__(256) void qkv_kernel(
    const float* __restrict__ x,
    const float* __restrict__ Wq, const float* __restrict__ bq,
    const float* __restrict__ Wk, const float* __restrict__ bk,
    const float* __restrict__ Wv, const float* __restrict__ bv)
{
    __shared__ float Xs[64*16];     // [row][k]
    __shared__ float Ws[16*192];    // [k][m*64+h]

    const int tid = threadIdx.x;
    const int tx = tid & 15;        // h-group: cols tx*4 in each of q,k,v
    const int ty = tid >> 4;        // rows ty*4
    const size_t row0 = (size_t)blockIdx.x * 64;

    // load-assignment indices
    const int lrow = tid >> 2;      // 0..63   (x tile)
    const int lkg  = tid & 3;       // 0..3
    const int wkk  = tid >> 4;      // 0..15   (W tiles)
    const int whg  = tid & 15;      // 0..15

    const float* xp  = x  + (row0 + lrow) * EE + lkg * 4;
    const float* wqp = Wq + wkk * HH + whg * 4;
    const float* wkp = Wk + wkk * HH + whg * 4;
    const float* wvp = Wv + wkk * HH + whg * 4;

    // prefetch k0 = 0
    float4 xr  = *(const float4*)xp;
    float4 wr0 = *(const float4*)wqp;
    float4 wr1 = *(const float4*)wkp;
    float4 wr2 = *(const float4*)wvp;

    float acc0[4][4], acc1[4][4], acc2[4][4];
    #pragma unroll
    for (int r = 0; r < 4; r++)
        #pragma unroll
        for (int c = 0; c < 4; c++) { acc0[r][c]=0.f; acc1[r][c]=0.f; acc2[r][c]=0.f; }

    for (int k0 = 0; k0 < EE; k0 += 16) {
        __syncthreads();                         // previous compute done reading smem
        *(float4*)&Xs[lrow*16 + lkg*4]          = xr;
        *(float4*)&Ws[wkk*192 +       whg*4]    = wr0;
        *(float4*)&Ws[wkk*192 +  64 + whg*4]    = wr1;
        *(float4*)&Ws[wkk*192 + 128 + whg*4]    = wr2;
        __syncthreads();

        if (k0 + 16 < EE) {                      // prefetch next step (overlaps compute)
            xr  = *(const float4*)(xp + k0 + 16);
            wr0 = *(const float4*)(wqp + (size_t)(k0 + 16) * HH);
            wr1 = *(const float4*)(wkp + (size_t)(k0 + 16) * HH);
            wr2 = *(const float4*)(wvp + (size_t)(k0 + 16) * HH);
        }

        #pragma unroll
        for (int kk = 0; kk < 16; kk++) {
            float a[4];
            #pragma unroll
            for (int r = 0; r < 4; r++) a[r] = Xs[(ty*4+r)*16 + kk];
            float bqv[4], bkv[4], bvv[4];
            *(float4*)bqv = *(const float4*)&Ws[kk*192 +       tx*4];
            *(float4*)bkv = *(const float4*)&Ws[kk*192 +  64 + tx*4];
            *(float4*)bvv = *(const float4*)&Ws[kk*192 + 128 + tx*4];
            #pragma unroll
            for (int r = 0; r < 4; r++) {
                #pragma unroll
                for (int c = 0; c < 4; c++) {
                    acc0[r][c] += a[r] * bqv[c];
                    acc1[r][c] += a[r] * bkv[c];
                    acc2[r][c] += a[r] * bvv[c];
                }
            }
        }
    }

    float4 b0 = *(const float4*)(bq + tx*4);
    float4 b1 = *(const float4*)(bk + tx*4);
    float4 b2 = *(const float4*)(bv + tx*4);
    #pragma unroll
    for (int r = 0; r < 4; r++) {
        size_t orow = (row0 + ty*4 + r) * HH + tx*4;
        float4 o;
        o.x = acc0[r][0]+b0.x; o.y = acc0[r][1]+b0.y; o.z = acc0[r][2]+b0.z; o.w = acc0[r][3]+b0.w;
        *(float4*)(g_q + orow) = o;
        o.x = acc1[r][0]+b1.x; o.y = acc1[r][1]+b1.y; o.z = acc1[r][2]+b1.z; o.w = acc1[r][3]+b1.w;
        *(float4*)(g_k + orow) = o;
        o.x = acc2[r][0]+b2.x; o.y = acc2[r][1]+b2.y; o.z = acc2[r][2]+b2.z; o.w = acc2[r][3]+b2.w;
        *(float4*)(g_v + orow) = o;
    }
}

// ---------------------------------------------------------------------------
// Kernel 2: causal flash attention. BM=32 q-rows, BN=64 kv-cols, 256 threads.
// grid = 64 x 8 = 512 CTAs -> one resident wave at 4 CTAs/SM.
// Warp w owns rows w*4..w*4+3; lane owns cols lane*2,+1. Softmax via shfl,
// m/l in registers, P tile warp-private (syncwarp only).
// Dynamic smem 51200 B.
// ---------------------------------------------------------------------------
#define QP 36   // Qs pitch   (16B-aligned float4 rows, conflict-free transpose store)
#define KP 66   // Ks pitch   (8B-aligned float2 rows, conflict-free transpose store)
#define PP 68   // Ps pitch   (16B-aligned float4 rows)

__global__ __launch_bounds__(256) void attn_kernel(float* __restrict__ out)
{
    extern __shared__ float smem[];
    float* Qs = smem;                 // [h][row]  64 x QP
    float* Ks = Qs + 64*QP;           // [h][j]    64 x KP
    float* Vs = Ks + 64*KP;           // [j][h]    64 x 64
    float* Ps = Vs + 64*64;           // [row][k]  32 x PP

    const int tid  = threadIdx.x;
    const int w    = tid >> 5;        // warp id: rows w*4..+3
    const int lane = tid & 31;        // cols lane*2, lane*2+1
    const int qt   = blockIdx.x;      // 0..63
    const int b    = blockIdx.y;      // 0..7

    // ---- load Q tile transposed: 32 rows x 64 h ----
    const float* qbase = g_q + ((size_t)b*TT + (size_t)qt*32) * HH;
    #pragma unroll
    for (int i = 0; i < 2; i++) {
        int idx = tid + i*256;        // 0..511
        int row = idx & 31;
        int hg  = idx >> 5;           // 0..15
        float4 v = *(const float4*)(qbase + (size_t)row*HH + hg*4);
        Qs[(hg*4+0)*QP + row] = v.x;
        Qs[(hg*4+1)*QP + row] = v.y;
        Qs[(hg*4+2)*QP + row] = v.z;
        Qs[(hg*4+3)*QP + row] = v.w;
    }

    float m[4], l[4], O[4][2];
    #pragma unroll
    for (int r = 0; r < 4; r++) {
        m[r] = -1e30f; l[r] = 0.f; O[r][0] = 0.f; O[r][1] = 0.f;
    }

    const float C = 0.18033688011112042f;   // (1/sqrt(64)) * log2(e)
    const int nt = (qt >> 1) + 1;           // kv tiles needed (causal)

    for (int kt = 0; kt < nt; kt++) {
        __syncthreads();   // protect Ks/Vs (and first-iter Qs) from prior readers

        // ---- load K (transposed) and V tiles: 64 rows x 64 h ----
        const float* kbase = g_k + ((size_t)b*TT + (size_t)kt*64) * HH;
        const float* vbase = g_v + ((size_t)b*TT + (size_t)kt*64) * HH;
        #pragma unroll
        for (int i = 0; i < 4; i++) {
            int idx = tid + i*256;    // 0..1023
            { // K: j = idx&63, hg = idx>>6  (conflict-free transpose store)
                int j  = idx & 63;
                int hg = idx >> 6;    // 0..15
                float4 kv = *(const float4*)(kbase + (size_t)j*HH + hg*4);
                Ks[(hg*4+0)*KP + j] = kv.x;
                Ks[(hg*4+1)*KP + j] = kv.y;
                Ks[(hg*4+2)*KP + j] = kv.z;
                Ks[(hg*4+3)*KP + j] = kv.w;
            }
            { // V: direct, coalesced
                int hg = idx & 15;
                int j  = idx >> 4;    // 0..63
                *(float4*)&Vs[j*64 + hg*4] =
                    *(const float4*)(vbase + (size_t)j*HH + hg*4);
            }
        }
        __syncthreads();

        // ---- S = Q @ K^T : 4 rows x 2 cols per thread ----
        float s[4][2];
        #pragma unroll
        for (int r = 0; r < 4; r++) { s[r][0] = 0.f; s[r][1] = 0.f; }
        #pragma unroll 16
        for (int h = 0; h < HH; h++) {
            float4 qv = *(const float4*)&Qs[h*QP + w*4];       // warp-uniform broadcast
            float2 kv = *(const float2*)&Ks[h*KP + lane*2];
            s[0][0] += qv.x*kv.x; s[0][1] += qv.x*kv.y;
            s[1][0] += qv.y*kv.x; s[1][1] += qv.y*kv.y;
            s[2][0] += qv.z*kv.x; s[2][1] += qv.z*kv.y;
            s[3][0] += qv.w*kv.x; s[3][1] += qv.w*kv.y;
        }

        // scale into log2 domain; mask only the (single) partial diagonal tile
        #pragma unroll
        for (int r = 0; r < 4; r++) { s[r][0] *= C; s[r][1] *= C; }
        if (kt == nt - 1) {
            int col = kt*64 + lane*2;
            #pragma unroll
            for (int r = 0; r < 4; r++) {
                int row = qt*32 + w*4 + r;
                if (col     > row) s[r][0] = -1e30f;
                if (col + 1 > row) s[r][1] = -1e30f;
            }
        }

        // ---- online softmax: warp-wide row reductions, state in registers ----
        #pragma unroll
        for (int r = 0; r < 4; r++) {
            float mt = fmaxf(s[r][0], s[r][1]);
            #pragma unroll
            for (int off = 16; off > 0; off >>= 1)
                mt = fmaxf(mt, __shfl_xor_sync(0xffffffffu, mt, off));
            float mnew = fmaxf(m[r], mt);
            float fr = exp2f(m[r] - mnew);
            float p0 = exp2f(s[r][0] - mnew);
            float p1 = exp2f(s[r][1] - mnew);
            m[r] = mnew;
            float sum = p0 + p1;
            #pragma unroll
            for (int off = 16; off > 0; off >>= 1)
                sum += __shfl_xor_sync(0xffffffffu, sum, off);
            l[r] = l[r]*fr + sum;
            O[r][0] *= fr; O[r][1] *= fr;
            *(float2*)&Ps[(w*4+r)*PP + lane*2] = make_float2(p0, p1);
        }
        __syncwarp();   // Ps rows are warp-private: cross-lane visibility only

        // ---- O += P @ V : 4 rows x 2 h-cols per thread ----
        #pragma unroll 4
        for (int k4 = 0; k4 < 64; k4 += 4) {
            float pr[4][4];
            #pragma unroll
            for (int r = 0; r < 4; r++)
                *(float4*)&pr[r][0] = *(const float4*)&Ps[(w*4+r)*PP + k4];
            #pragma unroll
            for (int kk = 0; kk < 4; kk++) {
                float2 vv = *(const float2*)&Vs[(k4+kk)*64 + lane*2];
                #pragma unroll
                for (int r = 0; r < 4; r++) {
                    O[r][0] += pr[r][kk] * vv.x;
                    O[r][1] += pr[r][kk] * vv.y;
                }
            }
        }
    }

    // ---- finalize ----
    #pragma unroll
    for (int r = 0; r < 4; r++) {
        float inv = 1.0f / l[r];
        size_t orow = ((size_t)b*TT + (size_t)qt*32 + w*4 + r) * HH + lane*2;
        *(float2*)(out + orow) = make_float2(O[r][0]*inv, O[r][1]*inv);
    }
}

// ---------------------------------------------------------------------------
extern "C" void kernel_launch(void* const* d_in, const int* in_sizes, int n_in,
                              void* d_out, int out_size)
{
    const float* x  = (const float*)d_in[0];
    const float* Wq = (const float*)d_in[1];
    const float* bq = (const float*)d_in[2];
    const float* Wk = (const float*)d_in[3];
    const float* bk = (const float*)d_in[4];
    const float* Wv = (const float*)d_in[5];
    const float* bv = (const float*)d_in[6];
    float* out = (float*)d_out;

    qkv_kernel<<<BB*TT/64, 256>>>(x, Wq, bq, Wk, bk, Wv, bv);

    const int smem_bytes = (64*QP + 64*KP + 64*64 + 32*PP) * 4;  // 51200
    cudaFuncSetAttribute(attn_kernel, cudaFuncAttributeMaxDynamicSharedMemorySize, smem_bytes);
    attn_kernel<<<dim3(TT/32, BB), 256, smem_bytes>>>(out);
}

// round 5
// speedup vs baseline: 2.4663x; 1.8242x over previous
#include <cuda_runtime.h>

#define BB 8
#define TT 2048
#define EE 1024
#define HH 64

// scratch for q,k,v projections (device globals: allocation-free)
__device__ float g_q[BB*TT*HH];
__device__ float g_k[BB*TT*HH];
__device__ float g_v[BB*TT*HH];

// ---------------------------------------------------------------------------
// Kernel 1: fused QKV projection (unchanged from R4 — proven, ~155us).
// ---------------------------------------------------------------------------
__global__ __launch_bounds__(256) void qkv_kernel(
    const float* __restrict__ x,
    const float* __restrict__ Wq, const float* __restrict__ bq,
    const float* __restrict__ Wk, const float* __restrict__ bk,
    const float* __restrict__ Wv, const float* __restrict__ bv)
{
    __shared__ float Xs[64*16];     // [row][k]
    __shared__ float Ws[16*192];    // [k][m*64+h]

    const int tid = threadIdx.x;
    const int tx = tid & 15;
    const int ty = tid >> 4;
    const size_t row0 = (size_t)blockIdx.x * 64;

    const int lrow = tid >> 2;
    const int lkg  = tid & 3;
    const int wkk  = tid >> 4;
    const int whg  = tid & 15;

    const float* xp  = x  + (row0 + lrow) * EE + lkg * 4;
    const float* wqp = Wq + wkk * HH + whg * 4;
    const float* wkp = Wk + wkk * HH + whg * 4;
    const float* wvp = Wv + wkk * HH + whg * 4;

    float4 xr  = *(const float4*)xp;
    float4 wr0 = *(const float4*)wqp;
    float4 wr1 = *(const float4*)wkp;
    float4 wr2 = *(const float4*)wvp;

    float acc0[4][4], acc1[4][4], acc2[4][4];
    #pragma unroll
    for (int r = 0; r < 4; r++)
        #pragma unroll
        for (int c = 0; c < 4; c++) { acc0[r][c]=0.f; acc1[r][c]=0.f; acc2[r][c]=0.f; }

    for (int k0 = 0; k0 < EE; k0 += 16) {
        __syncthreads();
        *(float4*)&Xs[lrow*16 + lkg*4]          = xr;
        *(float4*)&Ws[wkk*192 +       whg*4]    = wr0;
        *(float4*)&Ws[wkk*192 +  64 + whg*4]    = wr1;
        *(float4*)&Ws[wkk*192 + 128 + whg*4]    = wr2;
        __syncthreads();

        if (k0 + 16 < EE) {
            xr  = *(const float4*)(xp + k0 + 16);
            wr0 = *(const float4*)(wqp + (size_t)(k0 + 16) * HH);
            wr1 = *(const float4*)(wkp + (size_t)(k0 + 16) * HH);
            wr2 = *(const float4*)(wvp + (size_t)(k0 + 16) * HH);
        }

        #pragma unroll
        for (int kk = 0; kk < 16; kk++) {
            float a[4];
            #pragma unroll
            for (int r = 0; r < 4; r++) a[r] = Xs[(ty*4+r)*16 + kk];
            float bqv[4], bkv[4], bvv[4];
            *(float4*)bqv = *(const float4*)&Ws[kk*192 +       tx*4];
            *(float4*)bkv = *(const float4*)&Ws[kk*192 +  64 + tx*4];
            *(float4*)bvv = *(const float4*)&Ws[kk*192 + 128 + tx*4];
            #pragma unroll
            for (int r = 0; r < 4; r++) {
                #pragma unroll
                for (int c = 0; c < 4; c++) {
                    acc0[r][c] += a[r] * bqv[c];
                    acc1[r][c] += a[r] * bkv[c];
                    acc2[r][c] += a[r] * bvv[c];
                }
            }
        }
    }

    float4 b0 = *(const float4*)(bq + tx*4);
    float4 b1 = *(const float4*)(bk + tx*4);
    float4 b2 = *(const float4*)(bv + tx*4);
    #pragma unroll
    for (int r = 0; r < 4; r++) {
        size_t orow = (row0 + ty*4 + r) * HH + tx*4;
        float4 o;
        o.x = acc0[r][0]+b0.x; o.y = acc0[r][1]+b0.y; o.z = acc0[r][2]+b0.z; o.w = acc0[r][3]+b0.w;
        *(float4*)(g_q + orow) = o;
        o.x = acc1[r][0]+b1.x; o.y = acc1[r][1]+b1.y; o.z = acc1[r][2]+b1.z; o.w = acc1[r][3]+b1.w;
        *(float4*)(g_k + orow) = o;
        o.x = acc2[r][0]+b2.x; o.y = acc2[r][1]+b2.y; o.z = acc2[r][2]+b2.z; o.w = acc2[r][3]+b2.w;
        *(float4*)(g_v + orow) = o;
    }
}

// ---------------------------------------------------------------------------
// Kernel 2: causal flash attention with TF32 mma.sync (m16n8k8).
// BM = BN = 64. 128 threads = 4 warps; warp w owns q-rows w*16..w*16+15.
// CTA pair p processes q-tiles {p, 31-p}: 33 kv-tiles each -> balanced grid.
// K,V,P staged in smem at pitch 72 floats (stride mod 32 = 8 => every
// fragment access pattern g*8 + tig hits 32 distinct banks; conflict-free).
// Q fragments in registers, softmax scale * log2(e) folded in (exp2 domain).
// Online softmax state (m,l) in registers, quad shfl reductions.
// ---------------------------------------------------------------------------
#define KVP 72
#define NQT (TT/64)     // 32 q-tiles

__device__ __forceinline__ unsigned f2tf32(float x) {
    unsigned u;
    asm("cvt.rna.tf32.f32 %0, %1;" : "=r"(u) : "f"(x));
    return u;
}

__device__ __forceinline__ void mma_tf32(float c[4], const unsigned a[4],
                                         unsigned b0, unsigned b1) {
    asm volatile("mma.sync.aligned.m16n8k8.row.col.f32.tf32.tf32.f32 "
        "{%0,%1,%2,%3}, {%4,%5,%6,%7}, {%8,%9}, {%0,%1,%2,%3};"
        : "+f"(c[0]), "+f"(c[1]), "+f"(c[2]), "+f"(c[3])
        : "r"(a[0]), "r"(a[1]), "r"(a[2]), "r"(a[3]), "r"(b0), "r"(b1));
}

__global__ __launch_bounds__(128) void attn_kernel(float* __restrict__ out)
{
    extern __shared__ unsigned smemu[];
    unsigned* Ks = smemu;               // [j][h]  64 x KVP (tf32 bits)
    unsigned* Vs = Ks + 64*KVP;         // [j][h]  64 x KVP (tf32 bits)
    unsigned* Ps = Vs + 64*KVP;         // [r][j]  64 x KVP (tf32 bits)

    const int tid  = threadIdx.x;
    const int w    = tid >> 5;
    const int lane = tid & 31;
    const int g    = lane >> 2;         // 0..7
    const int tig  = lane & 3;          // 0..3
    const int pair = blockIdx.x;        // 0..15
    const int b    = blockIdx.y;        // 0..7

    const float CSC = 0.18033688011112042f;   // (1/sqrt(64)) * log2(e)

    #pragma unroll
    for (int phase = 0; phase < 2; phase++) {
        const int qt = phase ? (NQT - 1 - pair) : pair;

        // ---- Q fragments (A-layout) from gmem, scale folded, tf32 ----
        const float* qb = g_q + ((size_t)b*TT + (size_t)qt*64 + w*16) * HH;
        unsigned qa[8][4];
        #pragma unroll
        for (int kt = 0; kt < 8; kt++) {
            qa[kt][0] = f2tf32(qb[(size_t)g*HH     + kt*8 + tig    ] * CSC);
            qa[kt][1] = f2tf32(qb[(size_t)(g+8)*HH + kt*8 + tig    ] * CSC);
            qa[kt][2] = f2tf32(qb[(size_t)g*HH     + kt*8 + tig + 4] * CSC);
            qa[kt][3] = f2tf32(qb[(size_t)(g+8)*HH + kt*8 + tig + 4] * CSC);
        }

        float ma = -1e30f, mb = -1e30f, la = 0.f, lb = 0.f;
        float O[8][4];
        #pragma unroll
        for (int nt = 0; nt < 8; nt++)
            #pragma unroll
            for (int c = 0; c < 4; c++) O[nt][c] = 0.f;

        for (int kv = 0; kv <= qt; kv++) {
            __syncthreads();   // prior tile's readers done with Ks/Vs

            // ---- stage K,V tiles (convert fp32 -> tf32 once here) ----
            const float* kbase = g_k + ((size_t)b*TT + (size_t)kv*64) * HH;
            const float* vbase = g_v + ((size_t)b*TT + (size_t)kv*64) * HH;
            #pragma unroll
            for (int i = 0; i < 8; i++) {
                int idx = tid + i*128;          // 0..1023
                int j  = idx >> 4;              // 0..63
                int hg = idx & 15;              // 0..15
                float4 kf = *(const float4*)(kbase + (size_t)j*HH + hg*4);
                uint4 ku;
                ku.x = f2tf32(kf.x); ku.y = f2tf32(kf.y);
                ku.z = f2tf32(kf.z); ku.w = f2tf32(kf.w);
                *(uint4*)&Ks[j*KVP + hg*4] = ku;
                float4 vf = *(const float4*)(vbase + (size_t)j*HH + hg*4);
                uint4 vu;
                vu.x = f2tf32(vf.x); vu.y = f2tf32(vf.y);
                vu.z = f2tf32(vf.z); vu.w = f2tf32(vf.w);
                *(uint4*)&Vs[j*KVP + hg*4] = vu;
            }
            __syncthreads();

            // ---- S = Q @ K^T (exp2 domain; scale pre-folded in Q) ----
            float s[8][4];
            #pragma unroll
            for (int nt = 0; nt < 8; nt++)
                #pragma unroll
                for (int c = 0; c < 4; c++) s[nt][c] = 0.f;

            #pragma unroll
            for (int kt = 0; kt < 8; kt++) {
                #pragma unroll
                for (int nt = 0; nt < 8; nt++) {
                    unsigned b0 = Ks[(nt*8 + g)*KVP + kt*8 + tig    ];
                    unsigned b1 = Ks[(nt*8 + g)*KVP + kt*8 + tig + 4];
                    mma_tf32(s[nt], qa[kt], b0, b1);
                }
            }

            // ---- causal mask on diagonal tile ----
            if (kv == qt) {
                const int rowa = qt*64 + w*16 + g;
                #pragma unroll
                for (int nt = 0; nt < 8; nt++) {
                    int col = kv*64 + nt*8 + 2*tig;
                    if (col     > rowa    ) s[nt][0] = -1e30f;
                    if (col + 1 > rowa    ) s[nt][1] = -1e30f;
                    if (col     > rowa + 8) s[nt][2] = -1e30f;
                    if (col + 1 > rowa + 8) s[nt][3] = -1e30f;
                }
            }

            // ---- online softmax (quad-wide row reductions) ----
            float mxa = -1e30f, mxb = -1e30f;
            #pragma unroll
            for (int nt = 0; nt < 8; nt++) {
                mxa = fmaxf(mxa, fmaxf(s[nt][0], s[nt][1]));
                mxb = fmaxf(mxb, fmaxf(s[nt][2], s[nt][3]));
            }
            mxa = fmaxf(mxa, __shfl_xor_sync(0xffffffffu, mxa, 1));
            mxa = fmaxf(mxa, __shfl_xor_sync(0xffffffffu, mxa, 2));
            mxb = fmaxf(mxb, __shfl_xor_sync(0xffffffffu, mxb, 1));
            mxb = fmaxf(mxb, __shfl_xor_sync(0xffffffffu, mxb, 2));

            float mna = fmaxf(ma, mxa);
            float mnb = fmaxf(mb, mxb);
            float fa = exp2f(ma - mna);
            float fb = exp2f(mb - mnb);
            ma = mna; mb = mnb;

            float suma = 0.f, sumb = 0.f;
            const int pra = (w*16 + g)*KVP;
            const int prb = (w*16 + g + 8)*KVP;
            #pragma unroll
            for (int nt = 0; nt < 8; nt++) {
                float p0 = exp2f(s[nt][0] - mna);
                float p1 = exp2f(s[nt][1] - mna);
                float p2 = exp2f(s[nt][2] - mnb);
                float p3 = exp2f(s[nt][3] - mnb);
                suma += p0 + p1;
                sumb += p2 + p3;
                uint2 ua; ua.x = f2tf32(p0); ua.y = f2tf32(p1);
                *(uint2*)&Ps[pra + nt*8 + 2*tig] = ua;
                uint2 ub; ub.x = f2tf32(p2); ub.y = f2tf32(p3);
                *(uint2*)&Ps[prb + nt*8 + 2*tig] = ub;
            }
            suma += __shfl_xor_sync(0xffffffffu, suma, 1);
            suma += __shfl_xor_sync(0xffffffffu, suma, 2);
            sumb += __shfl_xor_sync(0xffffffffu, sumb, 1);
            sumb += __shfl_xor_sync(0xffffffffu, sumb, 2);
            la = la*fa + suma;
            lb = lb*fb + sumb;

            #pragma unroll
            for (int nt = 0; nt < 8; nt++) {
                O[nt][0] *= fa; O[nt][1] *= fa;
                O[nt][2] *= fb; O[nt][3] *= fb;
            }
            __syncwarp();   // Ps rows are warp-private: lane visibility only

            // ---- O += P @ V ----
            #pragma unroll
            for (int kt = 0; kt < 8; kt++) {
                unsigned pa[4];
                pa[0] = Ps[pra + kt*8 + tig    ];
                pa[1] = Ps[prb + kt*8 + tig    ];
                pa[2] = Ps[pra + kt*8 + tig + 4];
                pa[3] = Ps[prb + kt*8 + tig + 4];
                #pragma unroll
                for (int nt = 0; nt < 8; nt++) {
                    unsigned b0 = Vs[(kt*8 + tig    )*KVP + nt*8 + g];
                    unsigned b1 = Vs[(kt*8 + tig + 4)*KVP + nt*8 + g];
                    mma_tf32(O[nt], pa, b0, b1);
                }
            }
        }

        // ---- finalize ----
        float inva = 1.0f / la;
        float invb = 1.0f / lb;
        size_t ra = ((size_t)b*TT + (size_t)qt*64 + w*16 + g) * HH;
        size_t rb = ra + (size_t)8*HH;
        #pragma unroll
        for (int nt = 0; nt < 8; nt++) {
            float2 oa; oa.x = O[nt][0]*inva; oa.y = O[nt][1]*inva;
            *(float2*)(out + ra + nt*8 + 2*tig) = oa;
            float2 ob; ob.x = O[nt][2]*invb; ob.y = O[nt][3]*invb;
            *(float2*)(out + rb + nt*8 + 2*tig) = ob;
        }
    }
}

// ---------------------------------------------------------------------------
extern "C" void kernel_launch(void* const* d_in, const int* in_sizes, int n_in,
                              void* d_out, int out_size)
{
    const float* x  = (const float*)d_in[0];
    const float* Wq = (const float*)d_in[1];
    const float* bq = (const float*)d_in[2];
    const float* Wk = (const float*)d_in[3];
    const float* bk = (const float*)d_in[4];
    const float* Wv = (const float*)d_in[5];
    const float* bv = (const float*)d_in[6];
    float* out = (float*)d_out;

    qkv_kernel<<<BB*TT/64, 256>>>(x, Wq, bq, Wk, bk, Wv, bv);

    const int smem_bytes = 3 * 64 * KVP * 4;   // 55296
    cudaFuncSetAttribute(attn_kernel, cudaFuncAttributeMaxDynamicSharedMemorySize, smem_bytes);
    attn_kernel<<<dim3(NQT/2, BB), 128, smem_bytes>>>(out);
}

// round 10
// speedup vs baseline: 3.9128x; 1.5865x over previous
#include <cuda_runtime.h>
#include <cuda_bf16.h>
#include <cstdint>

#define BB 8
#define TT 2048
#define EE 1024
#define HH 64

// q (pre-scaled by CSC, tf32-rounded), k, v (tf32-rounded) scratch
__device__ float g_q[BB*TT*HH];
__device__ float g_k[BB*TT*HH];
__device__ float g_v[BB*TT*HH];

#define CSC 0.18033688011112042f   // (1/sqrt(64)) * log2(e)

// ---------------------------------------------------------------------------
// helpers
// ---------------------------------------------------------------------------
__device__ __forceinline__ unsigned f2tf32(float x) {
    unsigned u;
    asm("cvt.rna.tf32.f32 %0, %1;" : "=r"(u) : "f"(x));
    return u;
}
__device__ __forceinline__ float tf32r(float x) { return __uint_as_float(f2tf32(x)); }

__device__ __forceinline__ unsigned pack2bf(float a, float b) {
    __nv_bfloat162 t = __floats2bfloat162_rn(a, b);
    return *reinterpret_cast<unsigned*>(&t);
}

__device__ __forceinline__ unsigned smem_u32(const void* p) {
    unsigned a;
    asm("{ .reg .u64 t; cvta.to.shared.u64 t, %1; cvt.u32.u64 %0, t; }" : "=r"(a) : "l"(p));
    return a;
}
__device__ __forceinline__ void cp16(unsigned dst, const void* src) {
    asm volatile("cp.async.cg.shared.global [%0], [%1], 16;" :: "r"(dst), "l"(src));
}
__device__ __forceinline__ void cp_commit() { asm volatile("cp.async.commit_group;"); }
template<int N> __device__ __forceinline__ void cp_wait() {
    asm volatile("cp.async.wait_group %0;" :: "n"(N));
}

__device__ __forceinline__ void mma_bf16(float c[4], const unsigned a[4],
                                         unsigned b0, unsigned b1) {
    asm volatile("mma.sync.aligned.m16n8k16.row.col.f32.bf16.bf16.f32 "
        "{%0,%1,%2,%3}, {%4,%5,%6,%7}, {%8,%9}, {%0,%1,%2,%3};"
        : "+f"(c[0]), "+f"(c[1]), "+f"(c[2]), "+f"(c[3])
        : "r"(a[0]), "r"(a[1]), "r"(a[2]), "r"(a[3]), "r"(b0), "r"(b1));
}
__device__ __forceinline__ void mma_tf32(float c[4], const unsigned a[4],
                                         unsigned b0, unsigned b1) {
    asm volatile("mma.sync.aligned.m16n8k8.row.col.f32.tf32.tf32.f32 "
        "{%0,%1,%2,%3}, {%4,%5,%6,%7}, {%8,%9}, {%0,%1,%2,%3};"
        : "+f"(c[0]), "+f"(c[1]), "+f"(c[2]), "+f"(c[3])
        : "r"(a[0]), "r"(a[1]), "r"(a[2]), "r"(a[3]), "r"(b0), "r"(b1));
}

// ---------------------------------------------------------------------------
// Kernel 1: fused QKV projection via bf16x3 tensor-core GEMM.
// C[16384,192] = x[16384,1024] @ [Wq|Wk|Wv], bias added, outputs rounded to
// tf32 (q also pre-scaled by CSC) so attn can stage with raw copies.
// BM=128, BN=192, BK=64. 256 threads = 8 warps as 4 m-rows x 2 n-cols
// (m32 x n96 per warp). x,W split hi/lo bf16; 3 mma chains -> ~fp32 accuracy.
// Smem (packed bf16x2 uints): Xh/Xl 128x36, Wh/Wl 32x200  = 88064 B dynamic.
// ---------------------------------------------------------------------------
#define XP 36    // X pitch in uints (32 kpairs + pad)
#define WP 200   // W pitch in uints (192 cols + pad)

__global__ __launch_bounds__(256) void qkv_kernel(
    const float* __restrict__ x,
    const float* __restrict__ Wq, const float* __restrict__ bq,
    const float* __restrict__ Wk, const float* __restrict__ bk,
    const float* __restrict__ Wv, const float* __restrict__ bv)
{
    extern __shared__ unsigned sm[];
    unsigned* Xh = sm;                 // [row][kpair]
    unsigned* Xl = Xh + 128*XP;
    unsigned* Wh = Xl + 128*XP;        // [kpair][col]
    unsigned* Wl = Wh + 32*WP;

    const int tid  = threadIdx.x;
    const int w    = tid >> 5;
    const int lane = tid & 31;
    const int g    = lane >> 2;        // 0..7
    const int tig  = lane & 3;         // 0..3
    const int wm   = w >> 1;           // 0..3 : rows wm*32
    const int wn   = w & 1;            // 0..1 : cols wn*96
    const size_t row0 = (size_t)blockIdx.x * 128;

    float acc[2][12][4];
    #pragma unroll
    for (int s = 0; s < 2; s++)
        #pragma unroll
        for (int nf = 0; nf < 12; nf++)
            #pragma unroll
            for (int c = 0; c < 4; c++) acc[s][nf][c] = 0.f;

    for (int k0 = 0; k0 < EE; k0 += 64) {
        __syncthreads();
        // ---- stage X tile: 128 rows x 64 k, split hi/lo, pack k-pairs ----
        #pragma unroll
        for (int i = 0; i < 8; i++) {
            int idx = tid + i*256;             // 0..2047
            int r   = idx >> 4;                // 0..127
            int kq  = idx & 15;                // float4 index
            float4 f = *(const float4*)(x + (row0 + r)*EE + k0 + kq*4);
            float hx = __bfloat162float(__float2bfloat16_rn(f.x));
            float hy = __bfloat162float(__float2bfloat16_rn(f.y));
            float hz = __bfloat162float(__float2bfloat16_rn(f.z));
            float hw = __bfloat162float(__float2bfloat16_rn(f.w));
            uint2 uh, ul;
            uh.x = pack2bf(hx, hy);  uh.y = pack2bf(hz, hw);
            ul.x = pack2bf(f.x - hx, f.y - hy);
            ul.y = pack2bf(f.z - hz, f.w - hw);
            *(uint2*)&Xh[r*XP + 2*kq] = uh;
            *(uint2*)&Xl[r*XP + 2*kq] = ul;
        }
        // ---- stage W tile: 64 k x 192 cols (Wq|Wk|Wv), pack along k ----
        #pragma unroll
        for (int i = 0; i < 6; i++) {
            int idx = tid + i*256;             // 0..1535
            int kp  = idx / 48;                // 0..31 (k-pair)
            int c   = idx % 48;                // col quad
            int m   = c >> 4;                  // 0:q 1:k 2:v
            int col = (c & 15) * 4;
            const float* Wm = (m == 0) ? Wq : (m == 1 ? Wk : Wv);
            float4 f0 = *(const float4*)(Wm + (size_t)(k0 + 2*kp    )*HH + col);
            float4 f1 = *(const float4*)(Wm + (size_t)(k0 + 2*kp + 1)*HH + col);
            float h0x = __bfloat162float(__float2bfloat16_rn(f0.x));
            float h0y = __bfloat162float(__float2bfloat16_rn(f0.y));
            float h0z = __bfloat162float(__float2bfloat16_rn(f0.z));
            float h0w = __bfloat162float(__float2bfloat16_rn(f0.w));
            float h1x = __bfloat162float(__float2bfloat16_rn(f1.x));
            float h1y = __bfloat162float(__float2bfloat16_rn(f1.y));
            float h1z = __bfloat162float(__float2bfloat16_rn(f1.z));
            float h1w = __bfloat162float(__float2bfloat16_rn(f1.w));
            uint4 uh, ul;
            uh.x = pack2bf(h0x, h1x); uh.y = pack2bf(h0y, h1y);
            uh.z = pack2bf(h0z, h1z); uh.w = pack2bf(h0w, h1w);
            ul.x = pack2bf(f0.x - h0x, f1.x - h1x);
            ul.y = pack2bf(f0.y - h0y, f1.y - h1y);
            ul.z = pack2bf(f0.z - h0z, f1.z - h1z);
            ul.w = pack2bf(f0.w - h0w, f1.w - h1w);
            *(uint4*)&Wh[kp*WP + m*64 + col] = uh;
            *(uint4*)&Wl[kp*WP + m*64 + col] = ul;
        }
        __syncthreads();

        // ---- compute: 4 k16 steps ----
        #pragma unroll
        for (int kt = 0; kt < 4; kt++) {
            unsigned ah[2][4], al[2][4];
            #pragma unroll
            for (int s = 0; s < 2; s++) {
                int rb = wm*32 + s*16;
                ah[s][0] = Xh[(rb + g    )*XP + kt*8 + tig    ];
                ah[s][1] = Xh[(rb + g + 8)*XP + kt*8 + tig    ];
                ah[s][2] = Xh[(rb + g    )*XP + kt*8 + tig + 4];
                ah[s][3] = Xh[(rb + g + 8)*XP + kt*8 + tig + 4];
                al[s][0] = Xl[(rb + g    )*XP + kt*8 + tig    ];
                al[s][1] = Xl[(rb + g + 8)*XP + kt*8 + tig    ];
                al[s][2] = Xl[(rb + g    )*XP + kt*8 + tig + 4];
                al[s][3] = Xl[(rb + g + 8)*XP + kt*8 + tig + 4];
            }
            #pragma unroll
            for (int nf = 0; nf < 12; nf++) {
                int col = wn*96 + nf*8 + g;
                unsigned bh0 = Wh[(kt*8 + tig    )*WP + col];
                unsigned bh1 = Wh[(kt*8 + tig + 4)*WP + col];
                unsigned bl0 = Wl[(kt*8 + tig    )*WP + col];
                unsigned bl1 = Wl[(kt*8 + tig + 4)*WP + col];
                #pragma unroll
                for (int s = 0; s < 2; s++) {
                    mma_bf16(acc[s][nf], ah[s], bh0, bh1);
                    mma_bf16(acc[s][nf], al[s], bh0, bh1);
                    mma_bf16(acc[s][nf], ah[s], bl0, bl1);
                }
            }
        }
    }

    // ---- epilogue: bias, (scale), tf32-round, write ----
    #pragma unroll
    for (int nf = 0; nf < 12; nf++) {
        int cb   = wn*96 + nf*8;            // frag col base (never crosses 64-bound)
        int m    = cb >> 6;                 // 0:q 1:k 2:v
        int colm = cb + 2*tig - m*64;
        const float* bias = (m == 0) ? bq : (m == 1 ? bk : bv);
        float* outp       = (m == 0) ? g_q : (m == 1 ? g_k : g_v);
        float b0v = bias[colm], b1v = bias[colm + 1];
        #pragma unroll
        for (int s = 0; s < 2; s++) {
            size_t r0 = row0 + wm*32 + s*16 + g;
            float v00 = acc[s][nf][0] + b0v, v01 = acc[s][nf][1] + b1v;
            float v10 = acc[s][nf][2] + b0v, v11 = acc[s][nf][3] + b1v;
            if (m == 0) { v00 *= CSC; v01 *= CSC; v10 *= CSC; v11 *= CSC; }
            *(float2*)(outp + r0*HH + colm)       = make_float2(tf32r(v00), tf32r(v01));
            *(float2*)(outp + (r0+8)*HH + colm)   = make_float2(tf32r(v10), tf32r(v11));
        }
    }
}

// ---------------------------------------------------------------------------
// Kernel 2: causal flash attention, TF32 mma, cp.async double-buffered K/V.
// Inputs are pre-tf32-rounded (q pre-scaled) -> staging is a raw 16B copy.
// BM=BN=64, 128 threads; CTA pair p does q-tiles {p, 31-p} (33 kv-tiles).
// Smem: 2 stages x (K 64x72 + V 64x72) + P 64x72 = 92160 B dynamic.
// ---------------------------------------------------------------------------
#define KVP 72
#define NQT (TT/64)
#define STAGE_U (2*64*KVP)      // uints per stage (K+V)

__global__ __launch_bounds__(128) void attn_kernel(float* __restrict__ out)
{
    extern __shared__ unsigned smu[];
    unsigned* Ps = smu + 2*STAGE_U;     // [r][j] 64 x KVP
    const unsigned smbase = smem_u32(smu);

    const int tid  = threadIdx.x;
    const int w    = tid >> 5;
    const int lane = tid & 31;
    const int g    = lane >> 2;
    const int tig  = lane & 3;
    const int pair = blockIdx.x;        // 0..15
    const int b    = blockIdx.y;        // 0..7

    #pragma unroll
    for (int phase = 0; phase < 2; phase++) {
        const int qt = phase ? (NQT - 1 - pair) : pair;

        // ---- Q fragments: pre-scaled, pre-rounded -> direct bit loads ----
        const float* qb = g_q + ((size_t)b*TT + (size_t)qt*64 + w*16) * HH;
        unsigned qa[8][4];
        #pragma unroll
        for (int kt = 0; kt < 8; kt++) {
            qa[kt][0] = __float_as_uint(qb[(size_t)g*HH     + kt*8 + tig    ]);
            qa[kt][1] = __float_as_uint(qb[(size_t)(g+8)*HH + kt*8 + tig    ]);
            qa[kt][2] = __float_as_uint(qb[(size_t)g*HH     + kt*8 + tig + 4]);
            qa[kt][3] = __float_as_uint(qb[(size_t)(g+8)*HH + kt*8 + tig + 4]);
        }

        float ma = -1e30f, mb = -1e30f, la = 0.f, lb = 0.f;
        float O[8][4];
        #pragma unroll
        for (int nt = 0; nt < 8; nt++)
            #pragma unroll
            for (int c = 0; c < 4; c++) O[nt][c] = 0.f;

        // prologue: stage tile 0 into buffer 0
        {
            const float* kb = g_k + ((size_t)b*TT) * HH;
            const float* vb = g_v + ((size_t)b*TT) * HH;
            #pragma unroll
            for (int i = 0; i < 8; i++) {
                int idx = tid + i*128;
                int j  = idx >> 4;
                int hg = idx & 15;
                unsigned off = (unsigned)(j*KVP + hg*4) * 4;
                cp16(smbase + off,            kb + (size_t)j*HH + hg*4);
                cp16(smbase + off + 64*KVP*4, vb + (size_t)j*HH + hg*4);
            }
            cp_commit();
        }

        for (int kv = 0; kv <= qt; kv++) {
            const int st = kv & 1;
            if (kv < qt) {   // stage next tile into the other buffer
                const float* kb = g_k + ((size_t)b*TT + (size_t)(kv+1)*64) * HH;
                const float* vb = g_v + ((size_t)b*TT + (size_t)(kv+1)*64) * HH;
                const unsigned sb = smbase + (unsigned)(st ^ 1) * STAGE_U * 4;
                #pragma unroll
                for (int i = 0; i < 8; i++) {
                    int idx = tid + i*128;
                    int j  = idx >> 4;
                    int hg = idx & 15;
                    unsigned off = (unsigned)(j*KVP + hg*4) * 4;
                    cp16(sb + off,            kb + (size_t)j*HH + hg*4);
                    cp16(sb + off + 64*KVP*4, vb + (size_t)j*HH + hg*4);
                }
                cp_commit();
                cp_wait<1>();
            } else {
                cp_wait<0>();
            }
            __syncthreads();

            const unsigned* Ks = smu + st*STAGE_U;
            const unsigned* Vs = Ks + 64*KVP;

            // ---- S = Q @ K^T ----
            float s[8][4];
            #pragma unroll
            for (int nt = 0; nt < 8; nt++)
                #pragma unroll
                for (int c = 0; c < 4; c++) s[nt][c] = 0.f;

            #pragma unroll
            for (int kt = 0; kt < 8; kt++) {
                #pragma unroll
                for (int nt = 0; nt < 8; nt++) {
                    unsigned b0 = Ks[(nt*8 + g)*KVP + kt*8 + tig    ];
                    unsigned b1 = Ks[(nt*8 + g)*KVP + kt*8 + tig + 4];
                    mma_tf32(s[nt], qa[kt], b0, b1);
                }
            }

            // ---- causal mask on diagonal tile ----
            if (kv == qt) {
                const int rowa = qt*64 + w*16 + g;
                #pragma unroll
                for (int nt = 0; nt < 8; nt++) {
                    int col = kv*64 + nt*8 + 2*tig;
                    if (col     > rowa    ) s[nt][0] = -1e30f;
                    if (col + 1 > rowa    ) s[nt][1] = -1e30f;
                    if (col     > rowa + 8) s[nt][2] = -1e30f;
                    if (col + 1 > rowa + 8) s[nt][3] = -1e30f;
                }
            }

            // ---- online softmax (quad-wide reductions, exp2 domain) ----
            float mxa = -1e30f, mxb = -1e30f;
            #pragma unroll
            for (int nt = 0; nt < 8; nt++) {
                mxa = fmaxf(mxa, fmaxf(s[nt][0], s[nt][1]));
                mxb = fmaxf(mxb, fmaxf(s[nt][2], s[nt][3]));
            }
            mxa = fmaxf(mxa, __shfl_xor_sync(0xffffffffu, mxa, 1));
            mxa = fmaxf(mxa, __shfl_xor_sync(0xffffffffu, mxa, 2));
            mxb = fmaxf(mxb, __shfl_xor_sync(0xffffffffu, mxb, 1));
            mxb = fmaxf(mxb, __shfl_xor_sync(0xffffffffu, mxb, 2));

            float mna = fmaxf(ma, mxa);
            float mnb = fmaxf(mb, mxb);
            float fa = exp2f(ma - mna);
            float fb = exp2f(mb - mnb);
            ma = mna; mb = mnb;

            float suma = 0.f, sumb = 0.f;
            const int pra = (w*16 + g)*KVP;
            const int prb = (w*16 + g + 8)*KVP;
            #pragma unroll
            for (int nt = 0; nt < 8; nt++) {
                float p0 = exp2f(s[nt][0] - mna);
                float p1 = exp2f(s[nt][1] - mna);
                float p2 = exp2f(s[nt][2] - mnb);
                float p3 = exp2f(s[nt][3] - mnb);
                suma += p0 + p1;
                sumb += p2 + p3;
                uint2 ua; ua.x = f2tf32(p0); ua.y = f2tf32(p1);
                *(uint2*)&Ps[pra + nt*8 + 2*tig] = ua;
                uint2 ub; ub.x = f2tf32(p2); ub.y = f2tf32(p3);
                *(uint2*)&Ps[prb + nt*8 + 2*tig] = ub;
            }
            suma += __shfl_xor_sync(0xffffffffu, suma, 1);
            suma += __shfl_xor_sync(0xffffffffu, suma, 2);
            sumb += __shfl_xor_sync(0xffffffffu, sumb, 1);
            sumb += __shfl_xor_sync(0xffffffffu, sumb, 2);
            la = la*fa + suma;
            lb = lb*fb + sumb;

            #pragma unroll
            for (int nt = 0; nt < 8; nt++) {
                O[nt][0] *= fa; O[nt][1] *= fa;
                O[nt][2] *= fb; O[nt][3] *= fb;
            }
            __syncwarp();

            // ---- O += P @ V ----
            #pragma unroll
            for (int kt = 0; kt < 8; kt++) {
                unsigned pa[4];
                pa[0] = Ps[pra + kt*8 + tig    ];
                pa[1] = Ps[prb + kt*8 + tig    ];
                pa[2] = Ps[pra + kt*8 + tig + 4];
                pa[3] = Ps[prb + kt*8 + tig + 4];
                #pragma unroll
                for (int nt = 0; nt < 8; nt++) {
                    unsigned b0 = Vs[(kt*8 + tig    )*KVP + nt*8 + g];
                    unsigned b1 = Vs[(kt*8 + tig + 4)*KVP + nt*8 + g];
                    mma_tf32(O[nt], pa, b0, b1);
                }
            }
            __syncthreads();   // all reads of this stage done before it is re-staged
        }

        // ---- finalize ----
        float inva = 1.0f / la;
        float invb = 1.0f / lb;
        size_t ra = ((size_t)b*TT + (size_t)qt*64 + w*16 + g) * HH;
        size_t rb = ra + (size_t)8*HH;
        #pragma unroll
        for (int nt = 0; nt < 8; nt++) {
            *(float2*)(out + ra + nt*8 + 2*tig) = make_float2(O[nt][0]*inva, O[nt][1]*inva);
            *(float2*)(out + rb + nt*8 + 2*tig) = make_float2(O[nt][2]*invb, O[nt][3]*invb);
        }
    }
}

// ---------------------------------------------------------------------------
extern "C" void kernel_launch(void* const* d_in, const int* in_sizes, int n_in,
                              void* d_out, int out_size)
{
    const float* x  = (const float*)d_in[0];
    const float* Wq = (const float*)d_in[1];
    const float* bq = (const float*)d_in[2];
    const float* Wk = (const float*)d_in[3];
    const float* bk = (const float*)d_in[4];
    const float* Wv = (const float*)d_in[5];
    const float* bv = (const float*)d_in[6];
    float* out = (float*)d_out;

    const int qkv_smem = (2*128*XP + 2*32*WP) * 4;          // 88064
    cudaFuncSetAttribute(qkv_kernel, cudaFuncAttributeMaxDynamicSharedMemorySize, qkv_smem);
    qkv_kernel<<<BB*TT/128, 256, qkv_smem>>>(x, Wq, bq, Wk, bk, Wv, bv);

    const int attn_smem = (2*STAGE_U + 64*KVP) * 4;         // 92160
    cudaFuncSetAttribute(attn_kernel, cudaFuncAttributeMaxDynamicSharedMemorySize, attn_smem);
    attn_kernel<<<dim3(NQT/2, BB), 128, attn_smem>>>(out);
}

// round 14
// speedup vs baseline: 4.5126x; 1.1533x over previous
#include <cuda_runtime.h>
#include <cuda_bf16.h>
#include <cuda_fp16.h>
#include <cstdint>

#define BB 8
#define TT 2048
#define EE 1024
#define HH 64

// q (pre-scaled by CSC, tf32-rounded), k, v (tf32-rounded) scratch
__device__ float g_q[BB*TT*HH];
__device__ float g_k[BB*TT*HH];
__device__ float g_v[BB*TT*HH];

#define CSC 0.18033688011112042f   // (1/sqrt(64)) * log2(e)

// ---------------------------------------------------------------------------
// helpers
// ---------------------------------------------------------------------------
__device__ __forceinline__ unsigned f2tf32(float x) {
    unsigned u;
    asm("cvt.rna.tf32.f32 %0, %1;" : "=r"(u) : "f"(x));
    return u;
}
__device__ __forceinline__ float tf32r(float x) { return __uint_as_float(f2tf32(x)); }

__device__ __forceinline__ unsigned pack2h(float a, float b) {
    __half2 t = __floats2half2_rn(a, b);
    return *reinterpret_cast<unsigned*>(&t);
}

__device__ __forceinline__ unsigned smem_u32(const void* p) {
    unsigned a;
    asm("{ .reg .u64 t; cvta.to.shared.u64 t, %1; cvt.u32.u64 %0, t; }" : "=r"(a) : "l"(p));
    return a;
}
__device__ __forceinline__ void cp16(unsigned dst, const void* src) {
    asm volatile("cp.async.cg.shared.global [%0], [%1], 16;" :: "r"(dst), "l"(src));
}
__device__ __forceinline__ void cp_commit() { asm volatile("cp.async.commit_group;"); }
template<int N> __device__ __forceinline__ void cp_wait() {
    asm volatile("cp.async.wait_group %0;" :: "n"(N));
}

__device__ __forceinline__ void mma_f16(float c[4], const unsigned a[4],
                                        unsigned b0, unsigned b1) {
    asm volatile("mma.sync.aligned.m16n8k16.row.col.f32.f16.f16.f32 "
        "{%0,%1,%2,%3}, {%4,%5,%6,%7}, {%8,%9}, {%0,%1,%2,%3};"
        : "+f"(c[0]), "+f"(c[1]), "+f"(c[2]), "+f"(c[3])
        : "r"(a[0]), "r"(a[1]), "r"(a[2]), "r"(a[3]), "r"(b0), "r"(b1));
}
__device__ __forceinline__ void mma_tf32(float c[4], const unsigned a[4],
                                         unsigned b0, unsigned b1) {
    asm volatile("mma.sync.aligned.m16n8k8.row.col.f32.tf32.tf32.f32 "
        "{%0,%1,%2,%3}, {%4,%5,%6,%7}, {%8,%9}, {%0,%1,%2,%3};"
        : "+f"(c[0]), "+f"(c[1]), "+f"(c[2]), "+f"(c[3])
        : "r"(a[0]), "r"(a[1]), "r"(a[2]), "r"(a[3]), "r"(b0), "r"(b1));
}

// ---------------------------------------------------------------------------
// Kernel 1: fused QKV projection via fp16x2 tensor-core GEMM.
// x = xh + xl (both fp16), W in fp16: C ~= Xh@Wf + Xl@Wf; the dropped
// x@(W - f16(W)) term is ~2^-12 relative (incoherent) -> well under budget.
// BM=128, BN=192, BK=64. 256 threads = 8 warps (4 m-rows x 2 n-cols).
// Outputs tf32-rounded (q pre-scaled by CSC) so attn stages with raw copies.
// Smem: Xh/Xl 128x36 + Wf 32x200 uints = 62464 B dynamic.
// ---------------------------------------------------------------------------
#define XP 36    // X pitch in uints (32 kpairs + pad)
#define WP 200   // W pitch in uints (192 cols + pad)

__global__ __launch_bounds__(256) void qkv_kernel(
    const float* __restrict__ x,
    const float* __restrict__ Wq, const float* __restrict__ bq,
    const float* __restrict__ Wk, const float* __restrict__ bk,
    const float* __restrict__ Wv, const float* __restrict__ bv)
{
    extern __shared__ unsigned sm[];
    unsigned* Xh = sm;                 // [row][kpair]
    unsigned* Xl = Xh + 128*XP;
    unsigned* Wf = Xl + 128*XP;        // [kpair][col]

    const int tid  = threadIdx.x;
    const int w    = tid >> 5;
    const int lane = tid & 31;
    const int g    = lane >> 2;        // 0..7
    const int tig  = lane & 3;         // 0..3
    const int wm   = w >> 1;           // 0..3 : rows wm*32
    const int wn   = w & 1;            // 0..1 : cols wn*96
    const size_t row0 = (size_t)blockIdx.x * 128;

    float acc[2][12][4];
    #pragma unroll
    for (int s = 0; s < 2; s++)
        #pragma unroll
        for (int nf = 0; nf < 12; nf++)
            #pragma unroll
            for (int c = 0; c < 4; c++) acc[s][nf][c] = 0.f;

    for (int k0 = 0; k0 < EE; k0 += 64) {
        __syncthreads();
        // ---- stage X tile: 128 rows x 64 k, split hi/lo fp16, pack k-pairs ----
        #pragma unroll
        for (int i = 0; i < 8; i++) {
            int idx = tid + i*256;             // 0..2047
            int r   = idx >> 4;                // 0..127
            int kq  = idx & 15;                // float4 index
            float4 f = *(const float4*)(x + (row0 + r)*EE + k0 + kq*4);
            float hx = __half2float(__float2half_rn(f.x));
            float hy = __half2float(__float2half_rn(f.y));
            float hz = __half2float(__float2half_rn(f.z));
            float hw = __half2float(__float2half_rn(f.w));
            uint2 uh, ul;
            uh.x = pack2h(hx, hy);  uh.y = pack2h(hz, hw);
            ul.x = pack2h(f.x - hx, f.y - hy);
            ul.y = pack2h(f.z - hz, f.w - hw);
            *(uint2*)&Xh[r*XP + 2*kq] = uh;
            *(uint2*)&Xl[r*XP + 2*kq] = ul;
        }
        // ---- stage W tile: 64 k x 192 cols (Wq|Wk|Wv), fp16, pack along k ----
        #pragma unroll
        for (int i = 0; i < 6; i++) {
            int idx = tid + i*256;             // 0..1535
            int kp  = idx / 48;                // 0..31 (k-pair)
            int c   = idx % 48;                // col quad
            int m   = c >> 4;                  // 0:q 1:k 2:v
            int col = (c & 15) * 4;
            const float* Wm = (m == 0) ? Wq : (m == 1 ? Wk : Wv);
            float4 f0 = *(const float4*)(Wm + (size_t)(k0 + 2*kp    )*HH + col);
            float4 f1 = *(const float4*)(Wm + (size_t)(k0 + 2*kp + 1)*HH + col);
            uint4 uh;
            uh.x = pack2h(f0.x, f1.x); uh.y = pack2h(f0.y, f1.y);
            uh.z = pack2h(f0.z, f1.z); uh.w = pack2h(f0.w, f1.w);
            *(uint4*)&Wf[kp*WP + m*64 + col] = uh;
        }
        __syncthreads();

        // ---- compute: 4 k16 steps x 2 passes (hi, lo) ----
        #pragma unroll
        for (int kt = 0; kt < 4; kt++) {
            unsigned ah[2][4], al[2][4];
            #pragma unroll
            for (int s = 0; s < 2; s++) {
                int rb = wm*32 + s*16;
                ah[s][0] = Xh[(rb + g    )*XP + kt*8 + tig    ];
                ah[s][1] = Xh[(rb + g + 8)*XP + kt*8 + tig    ];
                ah[s][2] = Xh[(rb + g    )*XP + kt*8 + tig + 4];
                ah[s][3] = Xh[(rb + g + 8)*XP + kt*8 + tig + 4];
                al[s][0] = Xl[(rb + g    )*XP + kt*8 + tig    ];
                al[s][1] = Xl[(rb + g + 8)*XP + kt*8 + tig    ];
                al[s][2] = Xl[(rb + g    )*XP + kt*8 + tig + 4];
                al[s][3] = Xl[(rb + g + 8)*XP + kt*8 + tig + 4];
            }
            #pragma unroll
            for (int nf = 0; nf < 12; nf++) {
                int col = wn*96 + nf*8 + g;
                unsigned b0 = Wf[(kt*8 + tig    )*WP + col];
                unsigned b1 = Wf[(kt*8 + tig + 4)*WP + col];
                #pragma unroll
                for (int s = 0; s < 2; s++) {
                    mma_f16(acc[s][nf], ah[s], b0, b1);
                    mma_f16(acc[s][nf], al[s], b0, b1);
                }
            }
        }
    }

    // ---- epilogue: bias, (scale), tf32-round, write ----
    #pragma unroll
    for (int nf = 0; nf < 12; nf++) {
        int cb   = wn*96 + nf*8;            // frag col base (never crosses 64-bound)
        int m    = cb >> 6;                 // 0:q 1:k 2:v
        int colm = cb + 2*tig - m*64;
        const float* bias = (m == 0) ? bq : (m == 1 ? bk : bv);
        float* outp       = (m == 0) ? g_q : (m == 1 ? g_k : g_v);
        float b0v = bias[colm], b1v = bias[colm + 1];
        #pragma unroll
        for (int s = 0; s < 2; s++) {
            size_t r0 = row0 + wm*32 + s*16 + g;
            float v00 = acc[s][nf][0] + b0v, v01 = acc[s][nf][1] + b1v;
            float v10 = acc[s][nf][2] + b0v, v11 = acc[s][nf][3] + b1v;
            if (m == 0) { v00 *= CSC; v01 *= CSC; v10 *= CSC; v11 *= CSC; }
            *(float2*)(outp + r0*HH + colm)       = make_float2(tf32r(v00), tf32r(v01));
            *(float2*)(outp + (r0+8)*HH + colm)   = make_float2(tf32r(v10), tf32r(v11));
        }
    }
}

// ---------------------------------------------------------------------------
// Kernel 2: causal flash attention, TF32 mma, cp.async double-buffered K/V.
// 256 threads = 8 warps in 2 groups: group 0 owns S cols 0-31 / O h 0-31,
// group 1 owns cols 32-63 / h 32-63; rows split 4-ways (m16 per warp).
// Softmax row stats: quad shfl + 2-float smem exchange per group pair;
// both groups then carry identical m/l. Per-warp mma halves, warps per SM
// double. Smem: 2 stages (K+V 64x72 each) + P 64x72 + 256 red = 93184 B.
// ---------------------------------------------------------------------------
#define KVP 72
#define NQT (TT/64)
#define STAGE_U (2*64*KVP)      // uints per stage (K+V)

__global__ __launch_bounds__(256) void attn_kernel(float* __restrict__ out)
{
    extern __shared__ unsigned smu[];
    unsigned* Ps = smu + 2*STAGE_U;         // [r][j] 64 x KVP
    float* Rm = (float*)(Ps + 64*KVP);      // [grp][row] partial max, 128
    float* Rs = Rm + 128;                   // [grp][row] partial sum, 128
    const unsigned smbase = smem_u32(smu);

    const int tid  = threadIdx.x;
    const int w    = tid >> 5;          // 0..7
    const int grp  = w >> 2;            // 0..1 : n-half
    const int wq   = w & 3;             // 0..3 : row quarter (m16)
    const int lane = tid & 31;
    const int g    = lane >> 2;
    const int tig  = lane & 3;
    const int pair = blockIdx.x;        // 0..15
    const int b    = blockIdx.y;        // 0..7

    #pragma unroll
    for (int phase = 0; phase < 2; phase++) {
        const int qt = phase ? (NQT - 1 - pair) : pair;

        // ---- Q fragments: pre-scaled, pre-rounded -> direct bit loads ----
        const float* qb = g_q + ((size_t)b*TT + (size_t)qt*64 + wq*16) * HH;
        unsigned qa[8][4];
        #pragma unroll
        for (int kt = 0; kt < 8; kt++) {
            qa[kt][0] = __float_as_uint(qb[(size_t)g*HH     + kt*8 + tig    ]);
            qa[kt][1] = __float_as_uint(qb[(size_t)(g+8)*HH + kt*8 + tig    ]);
            qa[kt][2] = __float_as_uint(qb[(size_t)g*HH     + kt*8 + tig + 4]);
            qa[kt][3] = __float_as_uint(qb[(size_t)(g+8)*HH + kt*8 + tig + 4]);
        }

        float ma = -1e30f, mb = -1e30f, la = 0.f, lb = 0.f;
        float O[4][4];
        #pragma unroll
        for (int nt = 0; nt < 4; nt++)
            #pragma unroll
            for (int c = 0; c < 4; c++) O[nt][c] = 0.f;

        const int rowa = wq*16 + g;         // local row (a-half)
        const int rowb = rowa + 8;
        const int pra  = rowa*KVP;
        const int prb  = rowb*KVP;

        // prologue: stage tile 0 into buffer 0
        {
            const float* kb = g_k + ((size_t)b*TT) * HH;
            const float* vb = g_v + ((size_t)b*TT) * HH;
            #pragma unroll
            for (int i = 0; i < 4; i++) {
                int idx = tid + i*256;
                int j  = idx >> 4;
                int hg = idx & 15;
                unsigned off = (unsigned)(j*KVP + hg*4) * 4;
                cp16(smbase + off,            kb + (size_t)j*HH + hg*4);
                cp16(smbase + off + 64*KVP*4, vb + (size_t)j*HH + hg*4);
            }
            cp_commit();
        }

        for (int kv = 0; kv <= qt; kv++) {
            const int st = kv & 1;
            if (kv < qt) {   // stage next tile into the other buffer
                const float* kb = g_k + ((size_t)b*TT + (size_t)(kv+1)*64) * HH;
                const float* vb = g_v + ((size_t)b*TT + (size_t)(kv+1)*64) * HH;
                const unsigned sb = smbase + (unsigned)(st ^ 1) * STAGE_U * 4;
                #pragma unroll
                for (int i = 0; i < 4; i++) {
                    int idx = tid + i*256;
                    int j  = idx >> 4;
                    int hg = idx & 15;
                    unsigned off = (unsigned)(j*KVP + hg*4) * 4;
                    cp16(sb + off,            kb + (size_t)j*HH + hg*4);
                    cp16(sb + off + 64*KVP*4, vb + (size_t)j*HH + hg*4);
                }
                cp_commit();
                cp_wait<1>();
            } else {
                cp_wait<0>();
            }
            __syncthreads();

            const unsigned* Ks = smu + st*STAGE_U;
            const unsigned* Vs = Ks + 64*KVP;

            // ---- S = Q @ K^T : this group's 32 cols ----
            float s[4][4];
            #pragma unroll
            for (int nt = 0; nt < 4; nt++)
                #pragma unroll
                for (int c = 0; c < 4; c++) s[nt][c] = 0.f;

            #pragma unroll
            for (int kt = 0; kt < 8; kt++) {
                #pragma unroll
                for (int nt = 0; nt < 4; nt++) {
                    int jrow = grp*32 + nt*8 + g;
                    unsigned b0 = Ks[jrow*KVP + kt*8 + tig    ];
                    unsigned b1 = Ks[jrow*KVP + kt*8 + tig + 4];
                    mma_tf32(s[nt], qa[kt], b0, b1);
                }
            }

            // ---- causal mask on diagonal tile ----
            if (kv == qt) {
                const int rga = qt*64 + rowa;
                #pragma unroll
                for (int nt = 0; nt < 4; nt++) {
                    int col = kv*64 + grp*32 + nt*8 + 2*tig;
                    if (col     > rga    ) s[nt][0] = -1e30f;
                    if (col + 1 > rga    ) s[nt][1] = -1e30f;
                    if (col     > rga + 8) s[nt][2] = -1e30f;
                    if (col + 1 > rga + 8) s[nt][3] = -1e30f;
                }
            }

            // ---- partial row max (quad shfl over this group's 32 cols) ----
            float mxa = -1e30f, mxb = -1e30f;
            #pragma unroll
            for (int nt = 0; nt < 4; nt++) {
                mxa = fmaxf(mxa, fmaxf(s[nt][0], s[nt][1]));
                mxb = fmaxf(mxb, fmaxf(s[nt][2], s[nt][3]));
            }
            mxa = fmaxf(mxa, __shfl_xor_sync(0xffffffffu, mxa, 1));
            mxa = fmaxf(mxa, __shfl_xor_sync(0xffffffffu, mxa, 2));
            mxb = fmaxf(mxb, __shfl_xor_sync(0xffffffffu, mxb, 1));
            mxb = fmaxf(mxb, __shfl_xor_sync(0xffffffffu, mxb, 2));
            Rm[grp*64 + rowa] = mxa;
            Rm[grp*64 + rowb] = mxb;
            __syncthreads();

            float mna = fmaxf(ma, fmaxf(mxa, Rm[(1-grp)*64 + rowa]));
            float mnb = fmaxf(mb, fmaxf(mxb, Rm[(1-grp)*64 + rowb]));
            float fa = exp2f(ma - mna);
            float fb = exp2f(mb - mnb);
            ma = mna; mb = mnb;

            // ---- exp, partial sums, P to smem ----
            float suma = 0.f, sumb = 0.f;
            #pragma unroll
            for (int nt = 0; nt < 4; nt++) {
                float p0 = exp2f(s[nt][0] - mna);
                float p1 = exp2f(s[nt][1] - mna);
                float p2 = exp2f(s[nt][2] - mnb);
                float p3 = exp2f(s[nt][3] - mnb);
                suma += p0 + p1;
                sumb += p2 + p3;
                int colo = grp*32 + nt*8 + 2*tig;
                uint2 ua; ua.x = f2tf32(p0); ua.y = f2tf32(p1);
                *(uint2*)&Ps[pra + colo] = ua;
                uint2 ub; ub.x = f2tf32(p2); ub.y = f2tf32(p3);
                *(uint2*)&Ps[prb + colo] = ub;
            }
            suma += __shfl_xor_sync(0xffffffffu, suma, 1);
            suma += __shfl_xor_sync(0xffffffffu, suma, 2);
            sumb += __shfl_xor_sync(0xffffffffu, sumb, 1);
            sumb += __shfl_xor_sync(0xffffffffu, sumb, 2);
            Rs[grp*64 + rowa] = suma;
            Rs[grp*64 + rowb] = sumb;
            __syncthreads();   // also makes full Ps rows visible for PV

            la = la*fa + suma + Rs[(1-grp)*64 + rowa];
            lb = lb*fb + sumb + Rs[(1-grp)*64 + rowb];

            #pragma unroll
            for (int nt = 0; nt < 4; nt++) {
                O[nt][0] *= fa; O[nt][1] *= fa;
                O[nt][2] *= fb; O[nt][3] *= fb;
            }

            // ---- O += P @ V : this group's 32 h-cols, full kv range ----
            #pragma unroll
            for (int kt = 0; kt < 8; kt++) {
                unsigned pa[4];
                pa[0] = Ps[pra + kt*8 + tig    ];
                pa[1] = Ps[prb + kt*8 + tig    ];
                pa[2] = Ps[pra + kt*8 + tig + 4];
                pa[3] = Ps[prb + kt*8 + tig + 4];
                #pragma unroll
                for (int nt = 0; nt < 4; nt++) {
                    int hcol = grp*32 + nt*8 + g;
                    unsigned b0 = Vs[(kt*8 + tig    )*KVP + hcol];
                    unsigned b1 = Vs[(kt*8 + tig + 4)*KVP + hcol];
                    mma_tf32(O[nt], pa, b0, b1);
                }
            }
            __syncthreads();   // all reads of this stage done before re-staging
        }

        // ---- finalize ----
        float inva = 1.0f / la;
        float invb = 1.0f / lb;
        size_t ra = ((size_t)b*TT + (size_t)qt*64 + rowa) * HH;
        size_t rb = ((size_t)b*TT + (size_t)qt*64 + rowb) * HH;
        #pragma unroll
        for (int nt = 0; nt < 4; nt++) {
            int colo = grp*32 + nt*8 + 2*tig;
            *(float2*)(out + ra + colo) = make_float2(O[nt][0]*inva, O[nt][1]*inva);
            *(float2*)(out + rb + colo) = make_float2(O[nt][2]*invb, O[nt][3]*invb);
        }
    }
}

// ---------------------------------------------------------------------------
extern "C" void kernel_launch(void* const* d_in, const int* in_sizes, int n_in,
                              void* d_out, int out_size)
{
    const float* x  = (const float*)d_in[0];
    const float* Wq = (const float*)d_in[1];
    const float* bq = (const float*)d_in[2];
    const float* Wk = (const float*)d_in[3];
    const float* bk = (const float*)d_in[4];
    const float* Wv = (const float*)d_in[5];
    const float* bv = (const float*)d_in[6];
    float* out = (float*)d_out;

    const int qkv_smem = (2*128*XP + 32*WP) * 4;            // 62464
    cudaFuncSetAttribute(qkv_kernel, cudaFuncAttributeMaxDynamicSharedMemorySize, qkv_smem);
    qkv_kernel<<<BB*TT/128, 256, qkv_smem>>>(x, Wq, bq, Wk, bk, Wv, bv);

    const int attn_smem = (2*STAGE_U + 64*KVP + 256) * 4;   // 93184
    cudaFuncSetAttribute(attn_kernel, cudaFuncAttributeMaxDynamicSharedMemorySize, attn_smem);
    attn_kernel<<<dim3(NQT/2, BB), 256, attn_smem>>>(out);
}

// round 16
// speedup vs baseline: 5.3160x; 1.1780x over previous
#include <cuda_runtime.h>
#include <cuda_bf16.h>
#include <cuda_fp16.h>
#include <cstdint>

#define BB 8
#define TT 2048
#define EE 1024
#define HH 64

// q (pre-scaled by CSC, tf32-rounded), k, v (tf32-rounded) scratch
__device__ float g_q[BB*TT*HH];
__device__ float g_k[BB*TT*HH];
__device__ float g_v[BB*TT*HH];

#define CSC 0.18033688011112042f   // (1/sqrt(64)) * log2(e)

// ---------------------------------------------------------------------------
// helpers
// ---------------------------------------------------------------------------
__device__ __forceinline__ unsigned f2tf32(float x) {
    unsigned u;
    asm("cvt.rna.tf32.f32 %0, %1;" : "=r"(u) : "f"(x));
    return u;
}
__device__ __forceinline__ float tf32r(float x) { return __uint_as_float(f2tf32(x)); }

__device__ __forceinline__ unsigned pack2h(float a, float b) {
    __half2 t = __floats2half2_rn(a, b);
    return *reinterpret_cast<unsigned*>(&t);
}

__device__ __forceinline__ unsigned smem_u32(const void* p) {
    unsigned a;
    asm("{ .reg .u64 t; cvta.to.shared.u64 t, %1; cvt.u32.u64 %0, t; }" : "=r"(a) : "l"(p));
    return a;
}
__device__ __forceinline__ void cp16(unsigned dst, const void* src) {
    asm volatile("cp.async.cg.shared.global [%0], [%1], 16;" :: "r"(dst), "l"(src));
}
__device__ __forceinline__ void cp_commit() { asm volatile("cp.async.commit_group;"); }
template<int N> __device__ __forceinline__ void cp_wait() {
    asm volatile("cp.async.wait_group %0;" :: "n"(N));
}

__device__ __forceinline__ void mma_f16(float c[4], const unsigned a[4],
                                        unsigned b0, unsigned b1) {
    asm volatile("mma.sync.aligned.m16n8k16.row.col.f32.f16.f16.f32 "
        "{%0,%1,%2,%3}, {%4,%5,%6,%7}, {%8,%9}, {%0,%1,%2,%3};"
        : "+f"(c[0]), "+f"(c[1]), "+f"(c[2]), "+f"(c[3])
        : "r"(a[0]), "r"(a[1]), "r"(a[2]), "r"(a[3]), "r"(b0), "r"(b1));
}
__device__ __forceinline__ void mma_tf32(float c[4], const unsigned a[4],
                                         unsigned b0, unsigned b1) {
    asm volatile("mma.sync.aligned.m16n8k8.row.col.f32.tf32.tf32.f32 "
        "{%0,%1,%2,%3}, {%4,%5,%6,%7}, {%8,%9}, {%0,%1,%2,%3};"
        : "+f"(c[0]), "+f"(c[1]), "+f"(c[2]), "+f"(c[3])
        : "r"(a[0]), "r"(a[1]), "r"(a[2]), "r"(a[3]), "r"(b0), "r"(b1));
}

// ---------------------------------------------------------------------------
// Kernel 1: fused QKV projection via fp16x2 tensor-core GEMM.
// BM=64 -> grid 256 (was 128 on 148 SMs: chip partly idle). BN=192, BK=64.
// 256 threads = 8 warps (4 m16 rows x 2 n-cols of 96).
// x = xh + xl (fp16), W fp16; dropped x@(W-f16(W)) term ~2^-12 incoherent.
// Outputs tf32-rounded (q pre-scaled by CSC) so attn stages with raw copies.
// Smem: Xh/Xl 64x36 + Wf 32x200 uints = 44032 B dynamic.
// ---------------------------------------------------------------------------
#define XP 36    // X pitch in uints (32 kpairs + pad)
#define WP 200   // W pitch in uints (192 cols + pad)

__global__ __launch_bounds__(256) void qkv_kernel(
    const float* __restrict__ x,
    const float* __restrict__ Wq, const float* __restrict__ bq,
    const float* __restrict__ Wk, const float* __restrict__ bk,
    const float* __restrict__ Wv, const float* __restrict__ bv)
{
    extern __shared__ unsigned sm[];
    unsigned* Xh = sm;                 // [row][kpair]
    unsigned* Xl = Xh + 64*XP;
    unsigned* Wf = Xl + 64*XP;         // [kpair][col]

    const int tid  = threadIdx.x;
    const int w    = tid >> 5;
    const int lane = tid & 31;
    const int g    = lane >> 2;        // 0..7
    const int tig  = lane & 3;         // 0..3
    const int wm   = w >> 1;           // 0..3 : rows wm*16
    const int wn   = w & 1;            // 0..1 : cols wn*96
    const size_t row0 = (size_t)blockIdx.x * 64;

    float acc[12][4];
    #pragma unroll
    for (int nf = 0; nf < 12; nf++)
        #pragma unroll
        for (int c = 0; c < 4; c++) acc[nf][c] = 0.f;

    for (int k0 = 0; k0 < EE; k0 += 64) {
        __syncthreads();
        // ---- stage X tile: 64 rows x 64 k, split hi/lo fp16, pack k-pairs ----
        #pragma unroll
        for (int i = 0; i < 4; i++) {
            int idx = tid + i*256;             // 0..1023
            int r   = idx >> 4;                // 0..63
            int kq  = idx & 15;                // float4 index
            float4 f = *(const float4*)(x + (row0 + r)*EE + k0 + kq*4);
            float hx = __half2float(__float2half_rn(f.x));
            float hy = __half2float(__float2half_rn(f.y));
            float hz = __half2float(__float2half_rn(f.z));
            float hw = __half2float(__float2half_rn(f.w));
            uint2 uh, ul;
            uh.x = pack2h(hx, hy);  uh.y = pack2h(hz, hw);
            ul.x = pack2h(f.x - hx, f.y - hy);
            ul.y = pack2h(f.z - hz, f.w - hw);
            *(uint2*)&Xh[r*XP + 2*kq] = uh;
            *(uint2*)&Xl[r*XP + 2*kq] = ul;
        }
        // ---- stage W tile: 64 k x 192 cols (Wq|Wk|Wv), fp16, pack along k ----
        #pragma unroll
        for (int i = 0; i < 6; i++) {
            int idx = tid + i*256;             // 0..1535
            int kp  = idx / 48;                // 0..31 (k-pair)
            int c   = idx % 48;                // col quad
            int m   = c >> 4;                  // 0:q 1:k 2:v
            int col = (c & 15) * 4;
            const float* Wm = (m == 0) ? Wq : (m == 1 ? Wk : Wv);
            float4 f0 = *(const float4*)(Wm + (size_t)(k0 + 2*kp    )*HH + col);
            float4 f1 = *(const float4*)(Wm + (size_t)(k0 + 2*kp + 1)*HH + col);
            uint4 uh;
            uh.x = pack2h(f0.x, f1.x); uh.y = pack2h(f0.y, f1.y);
            uh.z = pack2h(f0.z, f1.z); uh.w = pack2h(f0.w, f1.w);
            *(uint4*)&Wf[kp*WP + m*64 + col] = uh;
        }
        __syncthreads();

        // ---- compute: 4 k16 steps x 2 passes (hi, lo) ----
        #pragma unroll
        for (int kt = 0; kt < 4; kt++) {
            unsigned ah[4], al[4];
            {
                int rb = wm*16;
                ah[0] = Xh[(rb + g    )*XP + kt*8 + tig    ];
                ah[1] = Xh[(rb + g + 8)*XP + kt*8 + tig    ];
                ah[2] = Xh[(rb + g    )*XP + kt*8 + tig + 4];
                ah[3] = Xh[(rb + g + 8)*XP + kt*8 + tig + 4];
                al[0] = Xl[(rb + g    )*XP + kt*8 + tig    ];
                al[1] = Xl[(rb + g + 8)*XP + kt*8 + tig    ];
                al[2] = Xl[(rb + g    )*XP + kt*8 + tig + 4];
                al[3] = Xl[(rb + g + 8)*XP + kt*8 + tig + 4];
            }
            #pragma unroll
            for (int nf = 0; nf < 12; nf++) {
                int col = wn*96 + nf*8 + g;
                unsigned b0 = Wf[(kt*8 + tig    )*WP + col];
                unsigned b1 = Wf[(kt*8 + tig + 4)*WP + col];
                mma_f16(acc[nf], ah, b0, b1);
                mma_f16(acc[nf], al, b0, b1);
            }
        }
    }

    // ---- epilogue: bias, (scale), tf32-round, write ----
    #pragma unroll
    for (int nf = 0; nf < 12; nf++) {
        int cb   = wn*96 + nf*8;            // frag col base (never crosses 64-bound)
        int m    = cb >> 6;                 // 0:q 1:k 2:v
        int colm = cb + 2*tig - m*64;
        const float* bias = (m == 0) ? bq : (m == 1 ? bk : bv);
        float* outp       = (m == 0) ? g_q : (m == 1 ? g_k : g_v);
        float b0v = bias[colm], b1v = bias[colm + 1];
        size_t r0 = row0 + wm*16 + g;
        float v00 = acc[nf][0] + b0v, v01 = acc[nf][1] + b1v;
        float v10 = acc[nf][2] + b0v, v11 = acc[nf][3] + b1v;
        if (m == 0) { v00 *= CSC; v01 *= CSC; v10 *= CSC; v11 *= CSC; }
        *(float2*)(outp + r0*HH + colm)     = make_float2(tf32r(v00), tf32r(v01));
        *(float2*)(outp + (r0+8)*HH + colm) = make_float2(tf32r(v10), tf32r(v11));
    }
}

// ---------------------------------------------------------------------------
// Kernel 2: causal flash attention (R10 proven version: 4 warps, warp-private
// softmax, cp.async double-buffered K/V). TF32 mma.
// BM=BN=64, 128 threads; CTA pair p does q-tiles {p, 31-p} (33 kv-tiles).
// Smem: 2 stages x (K 64x72 + V 64x72) + P 64x72 = 92160 B dynamic.
// ---------------------------------------------------------------------------
#define KVP 72
#define NQT (TT/64)
#define STAGE_U (2*64*KVP)      // uints per stage (K+V)

__global__ __launch_bounds__(128) void attn_kernel(float* __restrict__ out)
{
    extern __shared__ unsigned smu[];
    unsigned* Ps = smu + 2*STAGE_U;     // [r][j] 64 x KVP
    const unsigned smbase = smem_u32(smu);

    const int tid  = threadIdx.x;
    const int w    = tid >> 5;
    const int lane = tid & 31;
    const int g    = lane >> 2;
    const int tig  = lane & 3;
    const int pair = blockIdx.x;        // 0..15
    const int b    = blockIdx.y;        // 0..7

    #pragma unroll
    for (int phase = 0; phase < 2; phase++) {
        const int qt = phase ? (NQT - 1 - pair) : pair;

        // ---- Q fragments: pre-scaled, pre-rounded -> direct bit loads ----
        const float* qb = g_q + ((size_t)b*TT + (size_t)qt*64 + w*16) * HH;
        unsigned qa[8][4];
        #pragma unroll
        for (int kt = 0; kt < 8; kt++) {
            qa[kt][0] = __float_as_uint(qb[(size_t)g*HH     + kt*8 + tig    ]);
            qa[kt][1] = __float_as_uint(qb[(size_t)(g+8)*HH + kt*8 + tig    ]);
            qa[kt][2] = __float_as_uint(qb[(size_t)g*HH     + kt*8 + tig + 4]);
            qa[kt][3] = __float_as_uint(qb[(size_t)(g+8)*HH + kt*8 + tig + 4]);
        }

        float ma = -1e30f, mb = -1e30f, la = 0.f, lb = 0.f;
        float O[8][4];
        #pragma unroll
        for (int nt = 0; nt < 8; nt++)
            #pragma unroll
            for (int c = 0; c < 4; c++) O[nt][c] = 0.f;

        // prologue: stage tile 0 into buffer 0
        {
            const float* kb = g_k + ((size_t)b*TT) * HH;
            const float* vb = g_v + ((size_t)b*TT) * HH;
            #pragma unroll
            for (int i = 0; i < 8; i++) {
                int idx = tid + i*128;
                int j  = idx >> 4;
                int hg = idx & 15;
                unsigned off = (unsigned)(j*KVP + hg*4) * 4;
                cp16(smbase + off,            kb + (size_t)j*HH + hg*4);
                cp16(smbase + off + 64*KVP*4, vb + (size_t)j*HH + hg*4);
            }
            cp_commit();
        }

        for (int kv = 0; kv <= qt; kv++) {
            const int st = kv & 1;
            if (kv < qt) {   // stage next tile into the other buffer
                const float* kb = g_k + ((size_t)b*TT + (size_t)(kv+1)*64) * HH;
                const float* vb = g_v + ((size_t)b*TT + (size_t)(kv+1)*64) * HH;
                const unsigned sb = smbase + (unsigned)(st ^ 1) * STAGE_U * 4;
                #pragma unroll
                for (int i = 0; i < 8; i++) {
                    int idx = tid + i*128;
                    int j  = idx >> 4;
                    int hg = idx & 15;
                    unsigned off = (unsigned)(j*KVP + hg*4) * 4;
                    cp16(sb + off,            kb + (size_t)j*HH + hg*4);
                    cp16(sb + off + 64*KVP*4, vb + (size_t)j*HH + hg*4);
                }
                cp_commit();
                cp_wait<1>();
            } else {
                cp_wait<0>();
            }
            __syncthreads();

            const unsigned* Ks = smu + st*STAGE_U;
            const unsigned* Vs = Ks + 64*KVP;

            // ---- S = Q @ K^T ----
            float s[8][4];
            #pragma unroll
            for (int nt = 0; nt < 8; nt++)
                #pragma unroll
                for (int c = 0; c < 4; c++) s[nt][c] = 0.f;

            #pragma unroll
            for (int kt = 0; kt < 8; kt++) {
                #pragma unroll
                for (int nt = 0; nt < 8; nt++) {
                    unsigned b0 = Ks[(nt*8 + g)*KVP + kt*8 + tig    ];
                    unsigned b1 = Ks[(nt*8 + g)*KVP + kt*8 + tig + 4];
                    mma_tf32(s[nt], qa[kt], b0, b1);
                }
            }

            // ---- causal mask on diagonal tile ----
            if (kv == qt) {
                const int rowa = qt*64 + w*16 + g;
                #pragma unroll
                for (int nt = 0; nt < 8; nt++) {
                    int col = kv*64 + nt*8 + 2*tig;
                    if (col     > rowa    ) s[nt][0] = -1e30f;
                    if (col + 1 > rowa    ) s[nt][1] = -1e30f;
                    if (col     > rowa + 8) s[nt][2] = -1e30f;
                    if (col + 1 > rowa + 8) s[nt][3] = -1e30f;
                }
            }

            // ---- online softmax (quad-wide reductions, exp2 domain) ----
            float mxa = -1e30f, mxb = -1e30f;
            #pragma unroll
            for (int nt = 0; nt < 8; nt++) {
                mxa = fmaxf(mxa, fmaxf(s[nt][0], s[nt][1]));
                mxb = fmaxf(mxb, fmaxf(s[nt][2], s[nt][3]));
            }
            mxa = fmaxf(mxa, __shfl_xor_sync(0xffffffffu, mxa, 1));
            mxa = fmaxf(mxa, __shfl_xor_sync(0xffffffffu, mxa, 2));
            mxb = fmaxf(mxb, __shfl_xor_sync(0xffffffffu, mxb, 1));
            mxb = fmaxf(mxb, __shfl_xor_sync(0xffffffffu, mxb, 2));

            float mna = fmaxf(ma, mxa);
            float mnb = fmaxf(mb, mxb);
            float fa = exp2f(ma - mna);
            float fb = exp2f(mb - mnb);
            ma = mna; mb = mnb;

            float suma = 0.f, sumb = 0.f;
            const int pra = (w*16 + g)*KVP;
            const int prb = (w*16 + g + 8)*KVP;
            #pragma unroll
            for (int nt = 0; nt < 8; nt++) {
                float p0 = exp2f(s[nt][0] - mna);
                float p1 = exp2f(s[nt][1] - mna);
                float p2 = exp2f(s[nt][2] - mnb);
                float p3 = exp2f(s[nt][3] - mnb);
                suma += p0 + p1;
                sumb += p2 + p3;
                uint2 ua; ua.x = f2tf32(p0); ua.y = f2tf32(p1);
                *(uint2*)&Ps[pra + nt*8 + 2*tig] = ua;
                uint2 ub; ub.x = f2tf32(p2); ub.y = f2tf32(p3);
                *(uint2*)&Ps[prb + nt*8 + 2*tig] = ub;
            }
            suma += __shfl_xor_sync(0xffffffffu, suma, 1);
            suma += __shfl_xor_sync(0xffffffffu, suma, 2);
            sumb += __shfl_xor_sync(0xffffffffu, sumb, 1);
            sumb += __shfl_xor_sync(0xffffffffu, sumb, 2);
            la = la*fa + suma;
            lb = lb*fb + sumb;

            #pragma unroll
            for (int nt = 0; nt < 8; nt++) {
                O[nt][0] *= fa; O[nt][1] *= fa;
                O[nt][2] *= fb; O[nt][3] *= fb;
            }
            __syncwarp();   // Ps rows are warp-private: lane visibility only

            // ---- O += P @ V ----
            #pragma unroll
            for (int kt = 0; kt < 8; kt++) {
                unsigned pa[4];
                pa[0] = Ps[pra + kt*8 + tig    ];
                pa[1] = Ps[prb + kt*8 + tig    ];
                pa[2] = Ps[pra + kt*8 + tig + 4];
                pa[3] = Ps[prb + kt*8 + tig + 4];
                #pragma unroll
                for (int nt = 0; nt < 8; nt++) {
                    unsigned b0 = Vs[(kt*8 + tig    )*KVP + nt*8 + g];
                    unsigned b1 = Vs[(kt*8 + tig + 4)*KVP + nt*8 + g];
                    mma_tf32(O[nt], pa, b0, b1);
                }
            }
            __syncthreads();   // all reads of this stage done before re-staging
        }

        // ---- finalize ----
        float inva = 1.0f / la;
        float invb = 1.0f / lb;
        size_t ra = ((size_t)b*TT + (size_t)qt*64 + w*16 + g) * HH;
        size_t rb = ra + (size_t)8*HH;
        #pragma unroll
        for (int nt = 0; nt < 8; nt++) {
            *(float2*)(out + ra + nt*8 + 2*tig) = make_float2(O[nt][0]*inva, O[nt][1]*inva);
            *(float2*)(out + rb + nt*8 + 2*tig) = make_float2(O[nt][2]*invb, O[nt][3]*invb);
        }
    }
}

// ---------------------------------------------------------------------------
extern "C" void kernel_launch(void* const* d_in, const int* in_sizes, int n_in,
                              void* d_out, int out_size)
{
    const float* x  = (const float*)d_in[0];
    const float* Wq = (const float*)d_in[1];
    const float* bq = (const float*)d_in[2];
    const float* Wk = (const float*)d_in[3];
    const float* bk = (const float*)d_in[4];
    const float* Wv = (const float*)d_in[5];
    const float* bv = (const float*)d_in[6];
    float* out = (float*)d_out;

    const int qkv_smem = (2*64*XP + 32*WP) * 4;             // 44032
    cudaFuncSetAttribute(qkv_kernel, cudaFuncAttributeMaxDynamicSharedMemorySize, qkv_smem);
    qkv_kernel<<<BB*TT/64, 256, qkv_smem>>>(x, Wq, bq, Wk, bk, Wv, bv);

    const int attn_smem = (2*STAGE_U + 64*KVP) * 4;         // 92160
    cudaFuncSetAttribute(attn_kernel, cudaFuncAttributeMaxDynamicSharedMemorySize, attn_smem);
    attn_kernel<<<dim3(NQT/2, BB), 128, attn_smem>>>(out);
}

// round 17
// speedup vs baseline: 5.5168x; 1.0378x over previous
#include <cuda_runtime.h>
#include <cuda_bf16.h>
#include <cuda_fp16.h>
#include <cstdint>

#define BB 8
#define TT 2048
#define EE 1024
#define HH 64

// q (pre-scaled by CSC, tf32-rounded), k, v (tf32-rounded) scratch
__device__ float g_q[BB*TT*HH];
__device__ float g_k[BB*TT*HH];
__device__ float g_v[BB*TT*HH];

// split-kv partials: rows = q-tiles 16..31 => 8 batches x 1024 rows
__device__ float g_po[2][BB*1024*HH];   // unnormalized O
__device__ float g_pm[2][BB*1024];      // row max (exp2 domain)
__device__ float g_pl[2][BB*1024];      // row sum

#define CSC 0.18033688011112042f   // (1/sqrt(64)) * log2(e)

// ---------------------------------------------------------------------------
// helpers
// ---------------------------------------------------------------------------
__device__ __forceinline__ unsigned f2tf32(float x) {
    unsigned u;
    asm("cvt.rna.tf32.f32 %0, %1;" : "=r"(u) : "f"(x));
    return u;
}
__device__ __forceinline__ float tf32r(float x) { return __uint_as_float(f2tf32(x)); }

__device__ __forceinline__ unsigned pack2h(float a, float b) {
    __half2 t = __floats2half2_rn(a, b);
    return *reinterpret_cast<unsigned*>(&t);
}

__device__ __forceinline__ unsigned smem_u32(const void* p) {
    unsigned a;
    asm("{ .reg .u64 t; cvta.to.shared.u64 t, %1; cvt.u32.u64 %0, t; }" : "=r"(a) : "l"(p));
    return a;
}
__device__ __forceinline__ void cp16(unsigned dst, const void* src) {
    asm volatile("cp.async.cg.shared.global [%0], [%1], 16;" :: "r"(dst), "l"(src));
}
__device__ __forceinline__ void cp_commit() { asm volatile("cp.async.commit_group;"); }
template<int N> __device__ __forceinline__ void cp_wait() {
    asm volatile("cp.async.wait_group %0;" :: "n"(N));
}

__device__ __forceinline__ void mma_f16(float c[4], const unsigned a[4],
                                        unsigned b0, unsigned b1) {
    asm volatile("mma.sync.aligned.m16n8k16.row.col.f32.f16.f16.f32 "
        "{%0,%1,%2,%3}, {%4,%5,%6,%7}, {%8,%9}, {%0,%1,%2,%3};"
        : "+f"(c[0]), "+f"(c[1]), "+f"(c[2]), "+f"(c[3])
        : "r"(a[0]), "r"(a[1]), "r"(a[2]), "r"(a[3]), "r"(b0), "r"(b1));
}
__device__ __forceinline__ void mma_tf32(float c[4], const unsigned a[4],
                                         unsigned b0, unsigned b1) {
    asm volatile("mma.sync.aligned.m16n8k8.row.col.f32.tf32.tf32.f32 "
        "{%0,%1,%2,%3}, {%4,%5,%6,%7}, {%8,%9}, {%0,%1,%2,%3};"
        : "+f"(c[0]), "+f"(c[1]), "+f"(c[2]), "+f"(c[3])
        : "r"(a[0]), "r"(a[1]), "r"(a[2]), "r"(a[3]), "r"(b0), "r"(b1));
}

// ---------------------------------------------------------------------------
// Kernel 1: fused QKV projection via fp16x2 tensor-core GEMM (R16 proven).
// ---------------------------------------------------------------------------
#define XP 36    // X pitch in uints (32 kpairs + pad)
#define WP 200   // W pitch in uints (192 cols + pad)

__global__ __launch_bounds__(256) void qkv_kernel(
    const float* __restrict__ x,
    const float* __restrict__ Wq, const float* __restrict__ bq,
    const float* __restrict__ Wk, const float* __restrict__ bk,
    const float* __restrict__ Wv, const float* __restrict__ bv)
{
    extern __shared__ unsigned sm[];
    unsigned* Xh = sm;                 // [row][kpair]
    unsigned* Xl = Xh + 64*XP;
    unsigned* Wf = Xl + 64*XP;         // [kpair][col]

    const int tid  = threadIdx.x;
    const int w    = tid >> 5;
    const int lane = tid & 31;
    const int g    = lane >> 2;        // 0..7
    const int tig  = lane & 3;         // 0..3
    const int wm   = w >> 1;           // 0..3 : rows wm*16
    const int wn   = w & 1;            // 0..1 : cols wn*96
    const size_t row0 = (size_t)blockIdx.x * 64;

    float acc[12][4];
    #pragma unroll
    for (int nf = 0; nf < 12; nf++)
        #pragma unroll
        for (int c = 0; c < 4; c++) acc[nf][c] = 0.f;

    for (int k0 = 0; k0 < EE; k0 += 64) {
        __syncthreads();
        #pragma unroll
        for (int i = 0; i < 4; i++) {
            int idx = tid + i*256;             // 0..1023
            int r   = idx >> 4;                // 0..63
            int kq  = idx & 15;
            float4 f = *(const float4*)(x + (row0 + r)*EE + k0 + kq*4);
            float hx = __half2float(__float2half_rn(f.x));
            float hy = __half2float(__float2half_rn(f.y));
            float hz = __half2float(__float2half_rn(f.z));
            float hw = __half2float(__float2half_rn(f.w));
            uint2 uh, ul;
            uh.x = pack2h(hx, hy);  uh.y = pack2h(hz, hw);
            ul.x = pack2h(f.x - hx, f.y - hy);
            ul.y = pack2h(f.z - hz, f.w - hw);
            *(uint2*)&Xh[r*XP + 2*kq] = uh;
            *(uint2*)&Xl[r*XP + 2*kq] = ul;
        }
        #pragma unroll
        for (int i = 0; i < 6; i++) {
            int idx = tid + i*256;             // 0..1535
            int kp  = idx / 48;
            int c   = idx % 48;
            int m   = c >> 4;
            int col = (c & 15) * 4;
            const float* Wm = (m == 0) ? Wq : (m == 1 ? Wk : Wv);
            float4 f0 = *(const float4*)(Wm + (size_t)(k0 + 2*kp    )*HH + col);
            float4 f1 = *(const float4*)(Wm + (size_t)(k0 + 2*kp + 1)*HH + col);
            uint4 uh;
            uh.x = pack2h(f0.x, f1.x); uh.y = pack2h(f0.y, f1.y);
            uh.z = pack2h(f0.z, f1.z); uh.w = pack2h(f0.w, f1.w);
            *(uint4*)&Wf[kp*WP + m*64 + col] = uh;
        }
        __syncthreads();

        #pragma unroll
        for (int kt = 0; kt < 4; kt++) {
            unsigned ah[4], al[4];
            {
                int rb = wm*16;
                ah[0] = Xh[(rb + g    )*XP + kt*8 + tig    ];
                ah[1] = Xh[(rb + g + 8)*XP + kt*8 + tig    ];
                ah[2] = Xh[(rb + g    )*XP + kt*8 + tig + 4];
                ah[3] = Xh[(rb + g + 8)*XP + kt*8 + tig + 4];
                al[0] = Xl[(rb + g    )*XP + kt*8 + tig    ];
                al[1] = Xl[(rb + g + 8)*XP + kt*8 + tig    ];
                al[2] = Xl[(rb + g    )*XP + kt*8 + tig + 4];
                al[3] = Xl[(rb + g + 8)*XP + kt*8 + tig + 4];
            }
            #pragma unroll
            for (int nf = 0; nf < 12; nf++) {
                int col = wn*96 + nf*8 + g;
                unsigned b0 = Wf[(kt*8 + tig    )*WP + col];
                unsigned b1 = Wf[(kt*8 + tig + 4)*WP + col];
                mma_f16(acc[nf], ah, b0, b1);
                mma_f16(acc[nf], al, b0, b1);
            }
        }
    }

    #pragma unroll
    for (int nf = 0; nf < 12; nf++) {
        int cb   = wn*96 + nf*8;
        int m    = cb >> 6;
        int colm = cb + 2*tig - m*64;
        const float* bias = (m == 0) ? bq : (m == 1 ? bk : bv);
        float* outp       = (m == 0) ? g_q : (m == 1 ? g_k : g_v);
        float b0v = bias[colm], b1v = bias[colm + 1];
        size_t r0 = row0 + wm*16 + g;
        float v00 = acc[nf][0] + b0v, v01 = acc[nf][1] + b1v;
        float v10 = acc[nf][2] + b0v, v11 = acc[nf][3] + b1v;
        if (m == 0) { v00 *= CSC; v01 *= CSC; v10 *= CSC; v11 *= CSC; }
        *(float2*)(outp + r0*HH + colm)     = make_float2(tf32r(v00), tf32r(v01));
        *(float2*)(outp + (r0+8)*HH + colm) = make_float2(tf32r(v10), tf32r(v11));
    }
}

// ---------------------------------------------------------------------------
// Kernel 2: causal flash attention, split-KV. 1D grid 384, longest-first.
// Per batch (48 CTAs): j<16: part0 of qt=16+j (tiles 0..15); j==16: single
// qt=15; j==17: part1 of qt=31 (tiles 16..31); j>=18 pairs descending:
// l=15-((j-18)>>1): even -> single qt=l-1, odd -> part1 of qt=15+l.
// Body = R16 proven (4 warps, warp-private softmax, cp.async dbl buffer).
// part CTAs write unnormalized O + (m,l); singles write normalized out.
// ---------------------------------------------------------------------------
#define KVP 72
#define STAGE_U (2*64*KVP)      // uints per stage (K+V)

__global__ __launch_bounds__(128) void attn_kernel(float* __restrict__ out)
{
    extern __shared__ unsigned smu[];
    unsigned* Ps = smu + 2*STAGE_U;     // [r][j] 64 x KVP
    const unsigned smbase = smem_u32(smu);

    const int tid  = threadIdx.x;
    const int w    = tid >> 5;
    const int lane = tid & 31;
    const int g    = lane >> 2;
    const int tig  = lane & 3;

    // ---- decode (b, qt, part, kv range) from 1D bid, longest-first ----
    const int bid = blockIdx.x;
    const int b   = bid & 7;
    const int j   = bid >> 3;           // 0..47
    int qt, part, kv0, kv1;
    if (j < 16)       { qt = 16 + j; part = 0; kv0 = 0;  kv1 = 15; }
    else if (j == 16) { qt = 15;     part = 2; kv0 = 0;  kv1 = 15; }
    else if (j == 17) { qt = 31;     part = 1; kv0 = 16; kv1 = 31; }
    else {
        int l = 15 - ((j - 18) >> 1);
        if (((j - 18) & 1) == 0) { qt = l - 1;  part = 2; kv0 = 0;  kv1 = qt; }
        else                     { qt = 15 + l; part = 1; kv0 = 16; kv1 = qt; }
    }

    // ---- Q fragments: pre-scaled, pre-rounded -> direct bit loads ----
    const float* qb = g_q + ((size_t)b*TT + (size_t)qt*64 + w*16) * HH;
    unsigned qa[8][4];
    #pragma unroll
    for (int kt = 0; kt < 8; kt++) {
        qa[kt][0] = __float_as_uint(qb[(size_t)g*HH     + kt*8 + tig    ]);
        qa[kt][1] = __float_as_uint(qb[(size_t)(g+8)*HH + kt*8 + tig    ]);
        qa[kt][2] = __float_as_uint(qb[(size_t)g*HH     + kt*8 + tig + 4]);
        qa[kt][3] = __float_as_uint(qb[(size_t)(g+8)*HH + kt*8 + tig + 4]);
    }

    float ma = -1e30f, mb = -1e30f, la = 0.f, lb = 0.f;
    float O[8][4];
    #pragma unroll
    for (int nt = 0; nt < 8; nt++)
        #pragma unroll
        for (int c = 0; c < 4; c++) O[nt][c] = 0.f;

    // prologue: stage tile kv0 into buffer (kv0&1)
    {
        const float* kb = g_k + ((size_t)b*TT + (size_t)kv0*64) * HH;
        const float* vb = g_v + ((size_t)b*TT + (size_t)kv0*64) * HH;
        const unsigned sb = smbase + (unsigned)(kv0 & 1) * STAGE_U * 4;
        #pragma unroll
        for (int i = 0; i < 8; i++) {
            int idx = tid + i*128;
            int jj = idx >> 4;
            int hg = idx & 15;
            unsigned off = (unsigned)(jj*KVP + hg*4) * 4;
            cp16(sb + off,            kb + (size_t)jj*HH + hg*4);
            cp16(sb + off + 64*KVP*4, vb + (size_t)jj*HH + hg*4);
        }
        cp_commit();
    }

    for (int kv = kv0; kv <= kv1; kv++) {
        const int st = kv & 1;
        if (kv < kv1) {   // stage next tile into the other buffer
            const float* kb = g_k + ((size_t)b*TT + (size_t)(kv+1)*64) * HH;
            const float* vb = g_v + ((size_t)b*TT + (size_t)(kv+1)*64) * HH;
            const unsigned sb = smbase + (unsigned)(st ^ 1) * STAGE_U * 4;
            #pragma unroll
            for (int i = 0; i < 8; i++) {
                int idx = tid + i*128;
                int jj = idx >> 4;
                int hg = idx & 15;
                unsigned off = (unsigned)(jj*KVP + hg*4) * 4;
                cp16(sb + off,            kb + (size_t)jj*HH + hg*4);
                cp16(sb + off + 64*KVP*4, vb + (size_t)jj*HH + hg*4);
            }
            cp_commit();
            cp_wait<1>();
        } else {
            cp_wait<0>();
        }
        __syncthreads();

        const unsigned* Ks = smu + st*STAGE_U;
        const unsigned* Vs = Ks + 64*KVP;

        // ---- S = Q @ K^T ----
        float s[8][4];
        #pragma unroll
        for (int nt = 0; nt < 8; nt++)
            #pragma unroll
            for (int c = 0; c < 4; c++) s[nt][c] = 0.f;

        #pragma unroll
        for (int kt = 0; kt < 8; kt++) {
            #pragma unroll
            for (int nt = 0; nt < 8; nt++) {
                unsigned b0 = Ks[(nt*8 + g)*KVP + kt*8 + tig    ];
                unsigned b1 = Ks[(nt*8 + g)*KVP + kt*8 + tig + 4];
                mma_tf32(s[nt], qa[kt], b0, b1);
            }
        }

        // ---- causal mask on diagonal tile (only when kv == qt) ----
        if (kv == qt) {
            const int rowa = qt*64 + w*16 + g;
            #pragma unroll
            for (int nt = 0; nt < 8; nt++) {
                int col = kv*64 + nt*8 + 2*tig;
                if (col     > rowa    ) s[nt][0] = -1e30f;
                if (col + 1 > rowa    ) s[nt][1] = -1e30f;
                if (col     > rowa + 8) s[nt][2] = -1e30f;
                if (col + 1 > rowa + 8) s[nt][3] = -1e30f;
            }
        }

        // ---- online softmax (quad-wide reductions, exp2 domain) ----
        float mxa = -1e30f, mxb = -1e30f;
        #pragma unroll
        for (int nt = 0; nt < 8; nt++) {
            mxa = fmaxf(mxa, fmaxf(s[nt][0], s[nt][1]));
            mxb = fmaxf(mxb, fmaxf(s[nt][2], s[nt][3]));
        }
        mxa = fmaxf(mxa, __shfl_xor_sync(0xffffffffu, mxa, 1));
        mxa = fmaxf(mxa, __shfl_xor_sync(0xffffffffu, mxa, 2));
        mxb = fmaxf(mxb, __shfl_xor_sync(0xffffffffu, mxb, 1));
        mxb = fmaxf(mxb, __shfl_xor_sync(0xffffffffu, mxb, 2));

        float mna = fmaxf(ma, mxa);
        float mnb = fmaxf(mb, mxb);
        float fa = exp2f(ma - mna);
        float fb = exp2f(mb - mnb);
        ma = mna; mb = mnb;

        float suma = 0.f, sumb = 0.f;
        const int pra = (w*16 + g)*KVP;
        const int prb = (w*16 + g + 8)*KVP;
        #pragma unroll
        for (int nt = 0; nt < 8; nt++) {
            float p0 = exp2f(s[nt][0] - mna);
            float p1 = exp2f(s[nt][1] - mna);
            float p2 = exp2f(s[nt][2] - mnb);
            float p3 = exp2f(s[nt][3] - mnb);
            suma += p0 + p1;
            sumb += p2 + p3;
            uint2 ua; ua.x = f2tf32(p0); ua.y = f2tf32(p1);
            *(uint2*)&Ps[pra + nt*8 + 2*tig] = ua;
            uint2 ub; ub.x = f2tf32(p2); ub.y = f2tf32(p3);
            *(uint2*)&Ps[prb + nt*8 + 2*tig] = ub;
        }
        suma += __shfl_xor_sync(0xffffffffu, suma, 1);
        suma += __shfl_xor_sync(0xffffffffu, suma, 2);
        sumb += __shfl_xor_sync(0xffffffffu, sumb, 1);
        sumb += __shfl_xor_sync(0xffffffffu, sumb, 2);
        la = la*fa + suma;
        lb = lb*fb + sumb;

        #pragma unroll
        for (int nt = 0; nt < 8; nt++) {
            O[nt][0] *= fa; O[nt][1] *= fa;
            O[nt][2] *= fb; O[nt][3] *= fb;
        }
        __syncwarp();   // Ps rows are warp-private: lane visibility only

        // ---- O += P @ V ----
        #pragma unroll
        for (int kt = 0; kt < 8; kt++) {
            unsigned pa[4];
            pa[0] = Ps[pra + kt*8 + tig    ];
            pa[1] = Ps[prb + kt*8 + tig    ];
            pa[2] = Ps[pra + kt*8 + tig + 4];
            pa[3] = Ps[prb + kt*8 + tig + 4];
            #pragma unroll
            for (int nt = 0; nt < 8; nt++) {
                unsigned b0 = Vs[(kt*8 + tig    )*KVP + nt*8 + g];
                unsigned b1 = Vs[(kt*8 + tig + 4)*KVP + nt*8 + g];
                mma_tf32(O[nt], pa, b0, b1);
            }
        }
        __syncthreads();   // all reads of this stage done before re-staging
    }

    // ---- epilogue ----
    if (part == 2) {
        float inva = 1.0f / la;
        float invb = 1.0f / lb;
        size_t ra = ((size_t)b*TT + (size_t)qt*64 + w*16 + g) * HH;
        size_t rb = ra + (size_t)8*HH;
        #pragma unroll
        for (int nt = 0; nt < 8; nt++) {
            *(float2*)(out + ra + nt*8 + 2*tig) = make_float2(O[nt][0]*inva, O[nt][1]*inva);
            *(float2*)(out + rb + nt*8 + 2*tig) = make_float2(O[nt][2]*invb, O[nt][3]*invb);
        }
    } else {
        // partial rows within [b*1024 .. b*1024+1023]: (qt-16)*64 + local row
        size_t pr_a = (size_t)b*1024 + (size_t)(qt - 16)*64 + w*16 + g;
        size_t pr_b = pr_a + 8;
        float* po = g_po[part];
        #pragma unroll
        for (int nt = 0; nt < 8; nt++) {
            *(float2*)(po + pr_a*HH + nt*8 + 2*tig) = make_float2(O[nt][0], O[nt][1]);
            *(float2*)(po + pr_b*HH + nt*8 + 2*tig) = make_float2(O[nt][2], O[nt][3]);
        }
        if (tig == 0) {
            g_pm[part][pr_a] = ma;  g_pl[part][pr_a] = la;
            g_pm[part][pr_b] = mb;  g_pl[part][pr_b] = lb;
        }
    }
}

// ---------------------------------------------------------------------------
// Kernel 3: merge split-kv partials for q-tiles 16..31 (rows 1024.. per batch)
// ---------------------------------------------------------------------------
__global__ __launch_bounds__(256) void merge_kernel(float* __restrict__ out)
{
    int idx = blockIdx.x*256 + threadIdx.x;     // 0 .. 524287
    int col = idx & 63;
    int r   = idx >> 6;                         // 0..8191
    int b   = r >> 10;
    int lr  = r & 1023;
    float m0 = g_pm[0][r], m1 = g_pm[1][r];
    float l0 = g_pl[0][r], l1 = g_pl[1][r];
    float m  = fmaxf(m0, m1);
    float w0 = exp2f(m0 - m), w1 = exp2f(m1 - m);
    float l  = l0*w0 + l1*w1;
    float o  = (g_po[0][(size_t)r*HH + col]*w0 + g_po[1][(size_t)r*HH + col]*w1) / l;
    out[((size_t)b*TT + 1024 + lr)*HH + col] = o;
}

// ---------------------------------------------------------------------------
extern "C" void kernel_launch(void* const* d_in, const int* in_sizes, int n_in,
                              void* d_out, int out_size)
{
    const float* x  = (const float*)d_in[0];
    const float* Wq = (const float*)d_in[1];
    const float* bq = (const float*)d_in[2];
    const float* Wk = (const float*)d_in[3];
    const float* bk = (const float*)d_in[4];
    const float* Wv = (const float*)d_in[5];
    const float* bv = (const float*)d_in[6];
    float* out = (float*)d_out;

    const int qkv_smem = (2*64*XP + 32*WP) * 4;             // 44032
    cudaFuncSetAttribute(qkv_kernel, cudaFuncAttributeMaxDynamicSharedMemorySize, qkv_smem);
    qkv_kernel<<<BB*TT/64, 256, qkv_smem>>>(x, Wq, bq, Wk, bk, Wv, bv);

    const int attn_smem = (2*STAGE_U + 64*KVP) * 4;         // 92160
    cudaFuncSetAttribute(attn_kernel, cudaFuncAttributeMaxDynamicSharedMemorySize, attn_smem);
    attn_kernel<<<384, 128, attn_smem>>>(out);

    merge_kernel<<<BB*1024*HH/256, 256>>>(out);
}